// round 14
// baseline (speedup 1.0000x reference)
#include <cuda_runtime.h>
#include <cuda_fp16.h>
#include <stdint.h>
#include <math.h>

#define NN 100000
#define EE 3200000
#define HIDN 64

// ---------------- scratch (device globals; no allocation allowed) ----------------
__device__ __align__(128) __half g_mA[NN * HIDN];  // fp16 message ping (128B rows)
__device__ __align__(128) __half g_mB[NN * HIDN];  // fp16 message pong
__device__ __align__(16) float  g_hF[NN * HIDN];   // fp32 final-layer output
__device__ __align__(16) __half g_Wh[64 * 136];    // W_in transposed [n][k], fp16, LDA=136
__device__ __align__(16) int g_csr[EE];  // edge sources sorted by destination
__device__ __align__(16) int g_rank[EE]; // per-edge rank among same-destination edges
__device__ int   g_deg_in[NN];           // in-degree (no self loop)
__device__ int   g_off[NN];              // CSR offsets (exclusive scan of deg_in)
__device__ int   g_deg_out[NN];          // out-degree (structural)
__device__ float g_dis[NN];              // rsqrt(deg_in + 1)
__device__ float g_infl_sum[NN];
__device__ float g_infl[NN];
__device__ unsigned g_maxima[2];         // [0]=max out-degree bits, [1]=max infl bits
__device__ volatile int g_bsumv[128];    // scan block sums (published)
__device__ volatile int g_sflag[128];    // scan publish flags

// ---------------- init (+ W_in transpose/convert to fp16) ----------------
__global__ void k_init(const float* __restrict__ W, int n) {
    int i = blockIdx.x * blockDim.x + threadIdx.x;
    if (i < n) {
        g_deg_in[i] = 0;
        g_deg_out[i] = 0;
        g_infl_sum[i] = 0.f;
    }
    if (i < 2) g_maxima[i] = 0u;
    if (i < 128) { g_sflag[i] = 0; g_bsumv[i] = 0; }
    if (i < 128 * 64) {                      // coalesced read of W [k][n]
        int k = i >> 6, nn = i & 63;
        g_Wh[nn * 136 + k] = __float2half_rn(W[i]);
    }
}

// ---------------- degree histograms (+ edge rank capture), 2 edges/thread ----------------
__global__ void k_hist(const int* __restrict__ ei, int e) {
    int idx = (blockIdx.x * blockDim.x + threadIdx.x) * 2;
    if (idx >= e) return;
    if (idx + 1 < e) {
        int2 r2 = *reinterpret_cast<const int2*>(ei + idx);
        int2 c2 = *reinterpret_cast<const int2*>(ei + e + idx);
        g_rank[idx]     = atomicAdd(&g_deg_in[c2.x], 1);
        g_rank[idx + 1] = atomicAdd(&g_deg_in[c2.y], 1);
        atomicAdd(&g_deg_out[r2.x], 1);
        atomicAdd(&g_deg_out[r2.y], 1);
    } else {
        int r = ei[idx];
        int c = ei[e + idx];
        g_rank[idx] = atomicAdd(&g_deg_in[c], 1);
        atomicAdd(&g_deg_out[r], 1);
    }
}

// ---------------- single-kernel exclusive scan of deg_in + dis ----------------
// <= 98 blocks of 1024: guaranteed single wave on 148+ SMs -> spin-wait is safe.
__global__ void k_scan(int n) {
    __shared__ int s[1024];
    __shared__ int sPre;
    int tid = threadIdx.x;
    int b = blockIdx.x;
    int i = b * 1024 + tid;
    int val = (i < n) ? g_deg_in[i] : 0;
    if (i < n) g_dis[i] = rsqrtf((float)(val + 1));   // +1 for self loop
    s[tid] = val;
    __syncthreads();
    for (int off = 1; off < 1024; off <<= 1) {
        int t = 0;
        if (tid >= off) t = s[tid - off];
        __syncthreads();
        if (tid >= off) s[tid] += t;
        __syncthreads();
    }
    if (tid == 1023) {
        g_bsumv[b] = s[1023];
        __threadfence();
        g_sflag[b] = 1;
    }
    if (tid < 32) {
        int lane = tid;
        bool n0 = (lane      < b), n1 = (lane + 32 < b);
        bool n2 = (lane + 64 < b), n3 = (lane + 96 < b);
        while (true) {
            bool ok = (!n0 || g_sflag[lane]) && (!n1 || g_sflag[lane + 32]) &&
                      (!n2 || g_sflag[lane + 64]) && (!n3 || g_sflag[lane + 96]);
            if (__all_sync(0xffffffffu, ok)) break;
        }
        __threadfence();
        int pre = 0;
        if (n0) pre += g_bsumv[lane];
        if (n1) pre += g_bsumv[lane + 32];
        if (n2) pre += g_bsumv[lane + 64];
        if (n3) pre += g_bsumv[lane + 96];
#pragma unroll
        for (int o = 16; o; o >>= 1) pre += __shfl_down_sync(0xffffffffu, pre, o);
        if (lane == 0) sPre = pre;
    }
    __syncthreads();
    if (i < n) g_off[i] = s[tid] - val + sPre;   // global exclusive prefix
}

// ---------------- CSR scatter (atomic-free) + influence sums, 2 edges/thread ----------------
__global__ void k_scatter(const int* __restrict__ ei, int e) {
    int idx = (blockIdx.x * blockDim.x + threadIdx.x) * 2;
    if (idx >= e) return;
    if (idx + 1 < e) {
        int2 r2 = *reinterpret_cast<const int2*>(ei + idx);
        int2 c2 = *reinterpret_cast<const int2*>(ei + e + idx);
        int2 k2 = *reinterpret_cast<const int2*>(g_rank + idx);
        g_csr[g_off[c2.x] + k2.x] = r2.x;
        g_csr[g_off[c2.y] + k2.y] = r2.y;
        atomicAdd(&g_infl_sum[r2.x], (float)g_deg_out[c2.x]);
        atomicAdd(&g_infl_sum[r2.y], (float)g_deg_out[c2.y]);
    } else {
        int r = ei[idx];
        int c = ei[e + idx];
        g_csr[g_off[c] + g_rank[idx]] = r;
        atomicAdd(&g_infl_sum[r], (float)g_deg_out[c]);
    }
}

// ---------------- structural finalize (block-reduced maxima) ----------------
__global__ void k_struct(int n) {
    int v = blockIdx.x * blockDim.x + threadIdx.x;
    float degf = 0.f, infl = 0.f;
    if (v < n) {
        degf = (float)g_deg_out[v];
        infl = (degf > 0.f) ? (g_infl_sum[v] / degf) : 0.f;
        g_infl[v] = infl;
    }
#pragma unroll
    for (int off = 16; off; off >>= 1) {
        degf = fmaxf(degf, __shfl_down_sync(0xffffffffu, degf, off));
        infl = fmaxf(infl, __shfl_down_sync(0xffffffffu, infl, off));
    }
    __shared__ float sd[8], si[8];
    int lane = threadIdx.x & 31, wib = threadIdx.x >> 5;
    if (lane == 0) { sd[wib] = degf; si[wib] = infl; }
    __syncthreads();
    if (threadIdx.x == 0) {
        float md = sd[0], mi = si[0];
#pragma unroll
        for (int i = 1; i < 8; i++) { md = fmaxf(md, sd[i]); mi = fmaxf(mi, si[i]); }
        atomicMax(&g_maxima[0], __float_as_uint(md));
        atomicMax(&g_maxima[1], __float_as_uint(mi));
    }
}

// ---------------- tensor-core input GEMM ----------------
__global__ void __launch_bounds__(128) k_gemm_mma(
        const float* __restrict__ A, const float* __restrict__ bias,
        const float* __restrict__ rowscale, __half* __restrict__ C, int n) {
    constexpr int LDA = 136;   // halfs
    constexpr int LDC = 72;    // halfs
    __shared__ __align__(16) __half sA[64 * LDA];
    __shared__ __align__(16) __half sWt[64 * LDA];
    __shared__ float sBias[64];
    __half* sC = sA;

    const int tid = threadIdx.x;
    const int rowBase = blockIdx.x * 64;

    {
        const uint4* src = reinterpret_cast<const uint4*>(g_Wh);
        uint4* dst = reinterpret_cast<uint4*>(sWt);
        for (int i = tid; i < 64 * LDA / 8; i += 128) dst[i] = src[i];
    }
    if (tid < 64) sBias[tid] = bias[tid];

    for (int i = tid; i < 64 * 32; i += 128) {
        int r = i >> 5, c4 = i & 31;
        int gr = rowBase + r;
        float4 v = (gr < n) ? reinterpret_cast<const float4*>(A)[(size_t)gr * 32 + c4]
                            : make_float4(0.f, 0.f, 0.f, 0.f);
        __half2* d2 = reinterpret_cast<__half2*>(&sA[r * LDA + c4 * 4]);
        d2[0] = __floats2half2_rn(v.x, v.y);
        d2[1] = __floats2half2_rn(v.z, v.w);
    }
    __syncthreads();

    const int lane = tid & 31;
    const int warpM = tid >> 5;
    const int g = lane >> 2;
    const int tg = lane & 3;
    const int r0 = warpM * 16 + g;

    float acc[8][4];
#pragma unroll
    for (int nt = 0; nt < 8; nt++)
#pragma unroll
        for (int j = 0; j < 4; j++) acc[nt][j] = 0.f;

#pragma unroll
    for (int ks = 0; ks < 8; ks++) {
        const int kk = ks * 16;
        uint32_t a0 = *reinterpret_cast<const uint32_t*>(&sA[(r0)     * LDA + kk + tg * 2]);
        uint32_t a1 = *reinterpret_cast<const uint32_t*>(&sA[(r0 + 8) * LDA + kk + tg * 2]);
        uint32_t a2 = *reinterpret_cast<const uint32_t*>(&sA[(r0)     * LDA + kk + 8 + tg * 2]);
        uint32_t a3 = *reinterpret_cast<const uint32_t*>(&sA[(r0 + 8) * LDA + kk + 8 + tg * 2]);
#pragma unroll
        for (int nt = 0; nt < 8; nt++) {
            uint32_t b0 = *reinterpret_cast<const uint32_t*>(&sWt[(nt * 8 + g) * LDA + kk + tg * 2]);
            uint32_t b1 = *reinterpret_cast<const uint32_t*>(&sWt[(nt * 8 + g) * LDA + kk + 8 + tg * 2]);
            asm volatile(
                "mma.sync.aligned.m16n8k16.row.col.f32.f16.f16.f32 "
                "{%0,%1,%2,%3}, {%4,%5,%6,%7}, {%8,%9}, {%0,%1,%2,%3};"
                : "+f"(acc[nt][0]), "+f"(acc[nt][1]), "+f"(acc[nt][2]), "+f"(acc[nt][3])
                : "r"(a0), "r"(a1), "r"(a2), "r"(a3), "r"(b0), "r"(b1));
        }
    }
    __syncthreads();

    int grow0 = rowBase + r0, grow1 = grow0 + 8;
    float ds0 = (grow0 < n) ? rowscale[grow0] : 0.f;
    float ds1 = (grow1 < n) ? rowscale[grow1] : 0.f;
#pragma unroll
    for (int nt = 0; nt < 8; nt++) {
        int col = nt * 8 + tg * 2;
        float bx = sBias[col], by = sBias[col + 1];
        *reinterpret_cast<__half2*>(&sC[(r0)     * LDC + col]) =
            __floats2half2_rn((acc[nt][0] + bx) * ds0, (acc[nt][1] + by) * ds0);
        *reinterpret_cast<__half2*>(&sC[(r0 + 8) * LDC + col]) =
            __floats2half2_rn((acc[nt][2] + bx) * ds1, (acc[nt][3] + by) * ds1);
    }
    __syncthreads();

    for (int i = tid; i < 64 * 8; i += 128) {
        int r = i >> 3, q = i & 7;
        int gr = rowBase + r;
        if (gr < n) {
            uint4 v = *reinterpret_cast<const uint4*>(&sC[r * LDC + q * 8]);
            *reinterpret_cast<uint4*>(&C[(size_t)gr * 64 + q * 8]) = v;
        }
    }
}

// ---------------- fused GCN layer (fp16 messages + fp16 in-loop accumulation) --------------
// 4 nodes per warp. Quad-gather: lane group g=lane>>3 owns edge slot g, lane&7
// selects 8 columns (16B) -> one LDG.128 covers 4 edges. csr via int4.
// Accumulate in fp16 (HADD2); convert + group-combine (shfl-xor 8,16) in fp32 per node.
#define QUAD_ACC(r_)                                                                  \
    {                                                                                 \
        acc0 = __hadd2(acc0, *reinterpret_cast<__half2*>(&(r_).x));                   \
        acc1 = __hadd2(acc1, *reinterpret_cast<__half2*>(&(r_).y));                   \
        acc2 = __hadd2(acc2, *reinterpret_cast<__half2*>(&(r_).z));                   \
        acc3 = __hadd2(acc3, *reinterpret_cast<__half2*>(&(r_).w));                   \
    }

#define SINGLE_ACC(idx_)                                                              \
    {                                                                                 \
        uint4 _r = *reinterpret_cast<const uint4*>(mh + ((size_t)(idx_) << 6) + coff);\
        acc0 = __hfma2(*reinterpret_cast<__half2*>(&_r.x), mskh, acc0);               \
        acc1 = __hfma2(*reinterpret_cast<__half2*>(&_r.y), mskh, acc1);               \
        acc2 = __hfma2(*reinterpret_cast<__half2*>(&_r.z), mskh, acc2);               \
        acc3 = __hfma2(*reinterpret_cast<__half2*>(&_r.w), mskh, acc3);               \
    }

template <bool OUT_HALF>
__global__ void __launch_bounds__(256) k_layer(
        const __half* __restrict__ mh, void* __restrict__ hout,
        const float* __restrict__ W, const float* __restrict__ bias,
        const float* __restrict__ gamma, const float* __restrict__ beta, int n) {
    __shared__ __align__(16) float sW[64 * 64];      // 16 KB
    __shared__ __align__(16) float st[8][4][64];     // 8 KB
    __shared__ float sb[64], sg[64], sbt[64];
    const int tid = threadIdx.x;
    for (int i = tid; i < 64 * 64; i += 256) sW[i] = W[i];
    if (tid < 64) {
        sb[tid] = bias[tid];
        sg[tid] = gamma[tid] * rsqrtf(1.0f + 1e-5f);
        sbt[tid] = beta[tid];
    }
    __syncthreads();

    const int lane = tid & 31, wib = tid >> 5;
    const int vbase = blockIdx.x * 32 + wib * 4;
    const int grp = lane >> 3;                       // edge slot 0..3
    const size_t coff = (size_t)((lane & 7) << 3);   // half offset: 8 halfs per lane
    const __half2 mskh = (grp == 0) ? __floats2half2_rn(1.f, 1.f)
                                    : __floats2half2_rn(0.f, 0.f);

#pragma unroll
    for (int i = 0; i < 4; i++) {
        int v = vbase + i;
        __half2 acc0 = __floats2half2_rn(0.f, 0.f);
        __half2 acc1 = acc0, acc2 = acc0, acc3 = acc0;
        float dv = 0.f;
        if (v < n) {
            dv = g_dis[v];
            SINGLE_ACC(v);                           // self loop (group 0 only)
            int e = g_off[v];
            int end = e + g_deg_in[v];
            while ((e & 3) && e < end) {             // peel to int4 alignment
                SINGLE_ACC(g_csr[e]);
                e++;
            }
            for (; e + 4 <= end; e += 4) {           // 4 edges: 1 csr int4 + 1 quad LDG.128
                int4 q = *reinterpret_cast<const int4*>(g_csr + e);
                int idx = (grp == 0) ? q.x : (grp == 1) ? q.y : (grp == 2) ? q.z : q.w;
                uint4 r = *reinterpret_cast<const uint4*>(mh + ((size_t)idx << 6) + coff);
                QUAD_ACC(r);
            }
            while (e < end) {                        // tail <4
                SINGLE_ACC(g_csr[e]);
                e++;
            }
        }
        // fp32 convert + combine 4 groups
        float2 f0 = __half22float2(acc0), f1 = __half22float2(acc1);
        float2 f2 = __half22float2(acc2), f3 = __half22float2(acc3);
        float a[8] = {f0.x, f0.y, f1.x, f1.y, f2.x, f2.y, f3.x, f3.y};
#pragma unroll
        for (int k = 0; k < 8; k++) {
            a[k] += __shfl_xor_sync(0xffffffffu, a[k], 8);
            a[k] += __shfl_xor_sync(0xffffffffu, a[k], 16);
        }
        if (lane < 8) {
            float4* row4 = reinterpret_cast<float4*>(st[wib][i]);
            row4[lane * 2]     = make_float4(a[0] * dv, a[1] * dv, a[2] * dv, a[3] * dv);
            row4[lane * 2 + 1] = make_float4(a[4] * dv, a[5] * dv, a[6] * dv, a[7] * dv);
        }
    }
    __syncwarp();

    float o00 = sb[2 * lane], o01 = sb[2 * lane + 1];
    float o10 = o00, o11 = o01, o20 = o00, o21 = o01, o30 = o00, o31 = o01;
    const float2* sW2 = reinterpret_cast<const float2*>(sW);
#pragma unroll 8
    for (int k = 0; k < 64; k++) {
        float2 w = sW2[k * 32 + lane];
        float t0 = st[wib][0][k], t1 = st[wib][1][k], t2 = st[wib][2][k], t3 = st[wib][3][k];
        o00 = fmaf(t0, w.x, o00); o01 = fmaf(t0, w.y, o01);
        o10 = fmaf(t1, w.x, o10); o11 = fmaf(t1, w.y, o11);
        o20 = fmaf(t2, w.x, o20); o21 = fmaf(t2, w.y, o21);
        o30 = fmaf(t3, w.x, o30); o31 = fmaf(t3, w.y, o31);
    }

    float gx = sg[2 * lane], gy = sg[2 * lane + 1];
    float bx = sbt[2 * lane], by = sbt[2 * lane + 1];
    float ox[4] = {o00, o10, o20, o30};
    float oy[4] = {o01, o11, o21, o31};
#pragma unroll
    for (int i = 0; i < 4; i++) {
        int v = vbase + i;
        if (v < n) {
            float y0 = fmaxf(fmaf(ox[i], gx, bx), 0.f);
            float y1 = fmaxf(fmaf(oy[i], gy, by), 0.f);
            if (OUT_HALF) {
                float dv = g_dis[v];
                reinterpret_cast<__half2*>(hout)[(size_t)v * 32 + lane] =
                    __floats2half2_rn(y0 * dv, y1 * dv);
            } else {
                reinterpret_cast<float2*>(hout)[(size_t)v * 32 + lane] = make_float2(y0, y1);
            }
        }
    }
}

// ---------------- fused epilogue with tensor-core layer-1 ----------------
__global__ void __launch_bounds__(256) k_final(const float* __restrict__ h,
                        const float* __restrict__ Ws1, const float* __restrict__ bs1,
                        const float* __restrict__ Ws2, const float* __restrict__ bs2,
                        const float* __restrict__ Wo1, const float* __restrict__ bo1,
                        const float* __restrict__ Wo2, const float* __restrict__ bo2,
                        const float* __restrict__ Wo3, const float* __restrict__ bo3,
                        float* __restrict__ out, int n) {
    constexpr int LDZ = 136;   // halfs
    constexpr int LDY = 68;    // floats
    __shared__ __align__(16) __half sWt[64 * LDZ];
    __shared__ __align__(16) char  sZY[64 * LDZ * 2];
    __shared__ float sWo2[64 * 32];
    __shared__ float sbo1[64];
    __half* sZ = reinterpret_cast<__half*>(sZY);
    float*  sY1 = reinterpret_cast<float*>(sZY);

    const int tid = threadIdx.x;
    const int lane = tid & 31, wib = tid >> 5;
    const int vBase = blockIdx.x * 64;

    for (int i = tid; i < 128 * 64; i += 256) {
        int k = i >> 6, nn = i & 63;
        sWt[nn * LDZ + k] = __float2half_rn(Wo1[i]);
    }
    for (int i = tid; i < 64 * 32; i += 256) sWo2[i] = Wo2[i];
    if (tid < 64) sbo1[tid] = bo1[tid];

    float dmax = __uint_as_float(g_maxima[0]);
    float imax = __uint_as_float(g_maxima[1]);

#pragma unroll
    for (int i = 0; i < 8; i++) {
        int lr = wib * 8 + i;
        int v = vBase + lr;
        __half2* zrow = reinterpret_cast<__half2*>(&sZ[lr * LDZ]);
        if (v < n) {
            float degf = (float)g_deg_out[v];
            float inflv = g_infl[v];
            float sf0 = (dmax > 0.f) ? (degf / dmax) : degf;
            float sf2 = (imax > 0.f) ? (inflv / imax) : inflv;

            float hid = __ldg(&bs1[lane]) + sf0 * __ldg(&Ws1[lane]) + sf2 * __ldg(&Ws1[64 + lane]);
            hid = fmaxf(hid, 0.f);

            float se0 = __ldg(&bs2[2 * lane]);
            float se1 = __ldg(&bs2[2 * lane + 1]);
#pragma unroll
            for (int k = 0; k < 32; k++) {
                float hk = __shfl_sync(0xffffffffu, hid, k);
                float2 w = __ldg(reinterpret_cast<const float2*>(Ws2) + k * 32 + lane);
                se0 = fmaf(hk, w.x, se0);
                se1 = fmaf(hk, w.y, se1);
            }
            float2 hv = reinterpret_cast<const float2*>(h)[(size_t)v * 32 + lane];
            zrow[lane] = __floats2half2_rn(hv.x, hv.y);
            zrow[32 + lane] = __floats2half2_rn(se0, se1);
        } else {
            zrow[lane] = __floats2half2_rn(0.f, 0.f);
            zrow[32 + lane] = __floats2half2_rn(0.f, 0.f);
        }
    }
    __syncthreads();

    const int tileM = wib >> 1;
    const int nHalf = wib & 1;
    const int g = lane >> 2, tg = lane & 3;
    const int r0 = tileM * 16 + g;

    float acc[4][4];
#pragma unroll
    for (int nt = 0; nt < 4; nt++)
#pragma unroll
        for (int j = 0; j < 4; j++) acc[nt][j] = 0.f;

#pragma unroll
    for (int ks = 0; ks < 8; ks++) {
        const int kk = ks * 16;
        uint32_t a0 = *reinterpret_cast<const uint32_t*>(&sZ[(r0)     * LDZ + kk + tg * 2]);
        uint32_t a1 = *reinterpret_cast<const uint32_t*>(&sZ[(r0 + 8) * LDZ + kk + tg * 2]);
        uint32_t a2 = *reinterpret_cast<const uint32_t*>(&sZ[(r0)     * LDZ + kk + 8 + tg * 2]);
        uint32_t a3 = *reinterpret_cast<const uint32_t*>(&sZ[(r0 + 8) * LDZ + kk + 8 + tg * 2]);
#pragma unroll
        for (int nt = 0; nt < 4; nt++) {
            int brow = nHalf * 32 + nt * 8 + g;
            uint32_t b0 = *reinterpret_cast<const uint32_t*>(&sWt[brow * LDZ + kk + tg * 2]);
            uint32_t b1 = *reinterpret_cast<const uint32_t*>(&sWt[brow * LDZ + kk + 8 + tg * 2]);
            asm volatile(
                "mma.sync.aligned.m16n8k16.row.col.f32.f16.f16.f32 "
                "{%0,%1,%2,%3}, {%4,%5,%6,%7}, {%8,%9}, {%0,%1,%2,%3};"
                : "+f"(acc[nt][0]), "+f"(acc[nt][1]), "+f"(acc[nt][2]), "+f"(acc[nt][3])
                : "r"(a0), "r"(a1), "r"(a2), "r"(a3), "r"(b0), "r"(b1));
        }
    }
    __syncthreads();

#pragma unroll
    for (int nt = 0; nt < 4; nt++) {
        int col = nHalf * 32 + nt * 8 + tg * 2;
        float b0 = sbo1[col], b1 = sbo1[col + 1];
        sY1[(r0)     * LDY + col]     = fmaxf(acc[nt][0] + b0, 0.f);
        sY1[(r0)     * LDY + col + 1] = fmaxf(acc[nt][1] + b1, 0.f);
        sY1[(r0 + 8) * LDY + col]     = fmaxf(acc[nt][2] + b0, 0.f);
        sY1[(r0 + 8) * LDY + col + 1] = fmaxf(acc[nt][3] + b1, 0.f);
    }
    __syncthreads();

    float w3 = __ldg(&Wo3[lane]);
    float b2v = __ldg(&bo2[lane]);
    float b3 = __ldg(bo3);
#pragma unroll
    for (int j = 0; j < 4; j++) {
        int lr0 = wib * 8 + j * 2;
        int lr1 = lr0 + 1;
        float y20 = b2v, y21 = b2v;
        const float* y1a = &sY1[lr0 * LDY];
        const float* y1b = &sY1[lr1 * LDY];
#pragma unroll 16
        for (int k = 0; k < 64; k++) {
            float w2 = sWo2[k * 32 + lane];
            y20 = fmaf(y1a[k], w2, y20);
            y21 = fmaf(y1b[k], w2, y21);
        }
        y20 = fmaxf(y20, 0.f);
        y21 = fmaxf(y21, 0.f);
        float p0 = y20 * w3, p1 = y21 * w3;
#pragma unroll
        for (int off = 16; off; off >>= 1) {
            p0 += __shfl_down_sync(0xffffffffu, p0, off);
            p1 += __shfl_down_sync(0xffffffffu, p1, off);
        }
        if (lane == 0) {
            int v0 = vBase + lr0, v1 = vBase + lr1;
            if (v0 < n) out[v0] = 1.f / (1.f + expf(-(p0 + b3)));
            if (v1 < n) out[v1] = 1.f / (1.f + expf(-(p1 + b3)));
        }
    }
}

// ---------------- launch ----------------
extern "C" void kernel_launch(void* const* d_in, const int* in_sizes, int n_in,
                              void* d_out, int out_size) {
    const float* x     = (const float*)d_in[0];
    const int*   ei    = (const int*)  d_in[1];
    const float* W_in  = (const float*)d_in[2];
    const float* b_in  = (const float*)d_in[3];
    const float* W_gcn = (const float*)d_in[4];
    const float* b_gcn = (const float*)d_in[5];
    const float* gamma = (const float*)d_in[6];
    const float* beta  = (const float*)d_in[7];
    const float* Ws1   = (const float*)d_in[8];
    const float* bs1   = (const float*)d_in[9];
    const float* Ws2   = (const float*)d_in[10];
    const float* bs2   = (const float*)d_in[11];
    const float* Wo1   = (const float*)d_in[12];
    const float* bo1   = (const float*)d_in[13];
    const float* Wo2   = (const float*)d_in[14];
    const float* bo2   = (const float*)d_in[15];
    const float* Wo3   = (const float*)d_in[16];
    const float* bo3   = (const float*)d_in[17];
    float* out = (float*)d_out;

    int n = in_sizes[0] / 128;
    int e = in_sizes[1] / 2;
    if (n > NN) n = NN;
    if (e > EE) e = EE;

    void *pA_, *pB_, *pF_, *pDis_;
    cudaGetSymbolAddress(&pA_, g_mA);
    cudaGetSymbolAddress(&pB_, g_mB);
    cudaGetSymbolAddress(&pF_, g_hF);
    cudaGetSymbolAddress(&pDis_, g_dis);
    __half* pA = (__half*)pA_;
    __half* pB = (__half*)pB_;
    float*  pF = (float*)pF_;
    float*  pDis = (float*)pDis_;

    int nb_n = (n + 255) / 256;
    int nb_e2 = (e / 2 + 255) / 256 + 1;   // 2 edges/thread kernels
    int nb_s = (n + 1023) / 1024;
    int nb_f = (n + 63) / 64;      // k_final: 64 nodes/block
    int nb_l = (n + 31) / 32;      // k_layer: 32 nodes/block
    int nb_m = (n + 63) / 64;      // mma GEMM: 64 rows/block

    k_init<<<nb_n, 256>>>(W_in, n);        // 0
    k_hist<<<nb_e2, 256>>>(ei, e);         // 1 (also captures edge ranks)
    k_scan<<<nb_s, 1024>>>(n);             // 2 (single-wave lookback scan)
    k_scatter<<<nb_e2, 256>>>(ei, e);      // 3 <- ncu-sampled slot (atomic-free)
    k_struct<<<nb_n, 256>>>(n);            // 4

    // input projection (tensor cores): m0 = fp16(dis * (x @ W_in + b_in))
    k_gemm_mma<<<nb_m, 128>>>(x, b_in, pDis, pA, n);

    // 3 fused GCN layers (agg + GEMM + BN + relu); last layer writes fp32 h
    k_layer<true ><<<nb_l, 256>>>(pA, pB, W_gcn + 0 * 4096, b_gcn + 0 * 64, gamma + 0 * 64, beta + 0 * 64, n);
    k_layer<true ><<<nb_l, 256>>>(pB, pA, W_gcn + 1 * 4096, b_gcn + 1 * 64, gamma + 1 * 64, beta + 1 * 64, n);
    k_layer<false><<<nb_l, 256>>>(pA, pF, W_gcn + 2 * 4096, b_gcn + 2 * 64, gamma + 2 * 64, beta + 2 * 64, n);

    // structural MLP + concat + output MLP (tensor-core layer1) + sigmoid
    k_final<<<nb_f, 256>>>(pF, Ws1, bs1, Ws2, bs2, Wo1, bo1, Wo2, bo2, Wo3, bo3, out, n);
}

// round 15
// speedup vs baseline: 1.0991x; 1.0991x over previous
#include <cuda_runtime.h>
#include <cuda_fp16.h>
#include <stdint.h>
#include <math.h>

#define NN 100000
#define EE 3200000
#define HIDN 64

// ---------------- scratch (device globals; no allocation allowed) ----------------
__device__ __align__(128) __half g_mA[NN * HIDN];  // fp16 message ping (128B rows)
__device__ __align__(128) __half g_mB[NN * HIDN];  // fp16 message pong
__device__ __align__(16) float  g_hF[NN * HIDN];   // fp32 final-layer output
__device__ __align__(16) __half g_Wh[64 * 136];    // W_in transposed [n][k], fp16, LDA=136
__device__ __align__(16) int g_csr[EE];  // edge sources sorted by destination
__device__ __align__(16) int g_rank[EE]; // per-edge rank among same-destination edges
__device__ int   g_deg_in[NN];           // in-degree (no self loop)
__device__ int   g_off[NN];              // CSR offsets (exclusive scan of deg_in)
__device__ int   g_deg_out[NN];          // out-degree (structural)
__device__ float g_dis[NN];              // rsqrt(deg_in + 1)
__device__ float g_infl_sum[NN];
__device__ float g_infl[NN];
__device__ unsigned g_maxima[2];         // [0]=max out-degree bits, [1]=max infl bits
__device__ volatile int g_bsumv[128];    // scan block sums (published)
__device__ volatile int g_sflag[128];    // scan publish flags

// ---------------- init (+ W_in transpose/convert to fp16) ----------------
__global__ void k_init(const float* __restrict__ W, int n) {
    int i = blockIdx.x * blockDim.x + threadIdx.x;
    if (i < n) {
        g_deg_in[i] = 0;
        g_deg_out[i] = 0;
        g_infl_sum[i] = 0.f;
    }
    if (i < 2) g_maxima[i] = 0u;
    if (i < 128) { g_sflag[i] = 0; g_bsumv[i] = 0; }
    if (i < 128 * 64) {                      // coalesced read of W [k][n]
        int k = i >> 6, nn = i & 63;
        g_Wh[nn * 136 + k] = __float2half_rn(W[i]);
    }
}

// ---------------- degree histograms (+ edge rank capture), 2 edges/thread ----------------
__global__ void k_hist(const int* __restrict__ ei, int e) {
    int idx = (blockIdx.x * blockDim.x + threadIdx.x) * 2;
    if (idx >= e) return;
    if (idx + 1 < e) {
        int2 r2 = *reinterpret_cast<const int2*>(ei + idx);
        int2 c2 = *reinterpret_cast<const int2*>(ei + e + idx);
        g_rank[idx]     = atomicAdd(&g_deg_in[c2.x], 1);
        g_rank[idx + 1] = atomicAdd(&g_deg_in[c2.y], 1);
        atomicAdd(&g_deg_out[r2.x], 1);
        atomicAdd(&g_deg_out[r2.y], 1);
    } else {
        int r = ei[idx];
        int c = ei[e + idx];
        g_rank[idx] = atomicAdd(&g_deg_in[c], 1);
        atomicAdd(&g_deg_out[r], 1);
    }
}

// ---------------- single-kernel exclusive scan of deg_in + dis ----------------
// <= 98 blocks of 1024: guaranteed single wave on 148+ SMs -> spin-wait is safe.
__global__ void k_scan(int n) {
    __shared__ int s[1024];
    __shared__ int sPre;
    int tid = threadIdx.x;
    int b = blockIdx.x;
    int i = b * 1024 + tid;
    int val = (i < n) ? g_deg_in[i] : 0;
    if (i < n) g_dis[i] = rsqrtf((float)(val + 1));   // +1 for self loop
    s[tid] = val;
    __syncthreads();
    for (int off = 1; off < 1024; off <<= 1) {
        int t = 0;
        if (tid >= off) t = s[tid - off];
        __syncthreads();
        if (tid >= off) s[tid] += t;
        __syncthreads();
    }
    if (tid == 1023) {
        g_bsumv[b] = s[1023];
        __threadfence();
        g_sflag[b] = 1;
    }
    if (tid < 32) {
        int lane = tid;
        bool n0 = (lane      < b), n1 = (lane + 32 < b);
        bool n2 = (lane + 64 < b), n3 = (lane + 96 < b);
        while (true) {
            bool ok = (!n0 || g_sflag[lane]) && (!n1 || g_sflag[lane + 32]) &&
                      (!n2 || g_sflag[lane + 64]) && (!n3 || g_sflag[lane + 96]);
            if (__all_sync(0xffffffffu, ok)) break;
        }
        __threadfence();
        int pre = 0;
        if (n0) pre += g_bsumv[lane];
        if (n1) pre += g_bsumv[lane + 32];
        if (n2) pre += g_bsumv[lane + 64];
        if (n3) pre += g_bsumv[lane + 96];
#pragma unroll
        for (int o = 16; o; o >>= 1) pre += __shfl_down_sync(0xffffffffu, pre, o);
        if (lane == 0) sPre = pre;
    }
    __syncthreads();
    if (i < n) g_off[i] = s[tid] - val + sPre;   // global exclusive prefix
}

// ---------------- CSR scatter (atomic-free) + influence sums, 2 edges/thread ----------------
__global__ void k_scatter(const int* __restrict__ ei, int e) {
    int idx = (blockIdx.x * blockDim.x + threadIdx.x) * 2;
    if (idx >= e) return;
    if (idx + 1 < e) {
        int2 r2 = *reinterpret_cast<const int2*>(ei + idx);
        int2 c2 = *reinterpret_cast<const int2*>(ei + e + idx);
        int2 k2 = *reinterpret_cast<const int2*>(g_rank + idx);
        g_csr[g_off[c2.x] + k2.x] = r2.x;
        g_csr[g_off[c2.y] + k2.y] = r2.y;
        atomicAdd(&g_infl_sum[r2.x], (float)g_deg_out[c2.x]);
        atomicAdd(&g_infl_sum[r2.y], (float)g_deg_out[c2.y]);
    } else {
        int r = ei[idx];
        int c = ei[e + idx];
        g_csr[g_off[c] + g_rank[idx]] = r;
        atomicAdd(&g_infl_sum[r], (float)g_deg_out[c]);
    }
}

// ---------------- structural finalize (block-reduced maxima) ----------------
__global__ void k_struct(int n) {
    int v = blockIdx.x * blockDim.x + threadIdx.x;
    float degf = 0.f, infl = 0.f;
    if (v < n) {
        degf = (float)g_deg_out[v];
        infl = (degf > 0.f) ? (g_infl_sum[v] / degf) : 0.f;
        g_infl[v] = infl;
    }
#pragma unroll
    for (int off = 16; off; off >>= 1) {
        degf = fmaxf(degf, __shfl_down_sync(0xffffffffu, degf, off));
        infl = fmaxf(infl, __shfl_down_sync(0xffffffffu, infl, off));
    }
    __shared__ float sd[8], si[8];
    int lane = threadIdx.x & 31, wib = threadIdx.x >> 5;
    if (lane == 0) { sd[wib] = degf; si[wib] = infl; }
    __syncthreads();
    if (threadIdx.x == 0) {
        float md = sd[0], mi = si[0];
#pragma unroll
        for (int i = 1; i < 8; i++) { md = fmaxf(md, sd[i]); mi = fmaxf(mi, si[i]); }
        atomicMax(&g_maxima[0], __float_as_uint(md));
        atomicMax(&g_maxima[1], __float_as_uint(mi));
    }
}

// ---------------- tensor-core input GEMM ----------------
__global__ void __launch_bounds__(128) k_gemm_mma(
        const float* __restrict__ A, const float* __restrict__ bias,
        const float* __restrict__ rowscale, __half* __restrict__ C, int n) {
    constexpr int LDA = 136;   // halfs
    constexpr int LDC = 72;    // halfs
    __shared__ __align__(16) __half sA[64 * LDA];
    __shared__ __align__(16) __half sWt[64 * LDA];
    __shared__ float sBias[64];
    __half* sC = sA;

    const int tid = threadIdx.x;
    const int rowBase = blockIdx.x * 64;

    {
        const uint4* src = reinterpret_cast<const uint4*>(g_Wh);
        uint4* dst = reinterpret_cast<uint4*>(sWt);
        for (int i = tid; i < 64 * LDA / 8; i += 128) dst[i] = src[i];
    }
    if (tid < 64) sBias[tid] = bias[tid];

    for (int i = tid; i < 64 * 32; i += 128) {
        int r = i >> 5, c4 = i & 31;
        int gr = rowBase + r;
        float4 v = (gr < n) ? reinterpret_cast<const float4*>(A)[(size_t)gr * 32 + c4]
                            : make_float4(0.f, 0.f, 0.f, 0.f);
        __half2* d2 = reinterpret_cast<__half2*>(&sA[r * LDA + c4 * 4]);
        d2[0] = __floats2half2_rn(v.x, v.y);
        d2[1] = __floats2half2_rn(v.z, v.w);
    }
    __syncthreads();

    const int lane = tid & 31;
    const int warpM = tid >> 5;
    const int g = lane >> 2;
    const int tg = lane & 3;
    const int r0 = warpM * 16 + g;

    float acc[8][4];
#pragma unroll
    for (int nt = 0; nt < 8; nt++)
#pragma unroll
        for (int j = 0; j < 4; j++) acc[nt][j] = 0.f;

#pragma unroll
    for (int ks = 0; ks < 8; ks++) {
        const int kk = ks * 16;
        uint32_t a0 = *reinterpret_cast<const uint32_t*>(&sA[(r0)     * LDA + kk + tg * 2]);
        uint32_t a1 = *reinterpret_cast<const uint32_t*>(&sA[(r0 + 8) * LDA + kk + tg * 2]);
        uint32_t a2 = *reinterpret_cast<const uint32_t*>(&sA[(r0)     * LDA + kk + 8 + tg * 2]);
        uint32_t a3 = *reinterpret_cast<const uint32_t*>(&sA[(r0 + 8) * LDA + kk + 8 + tg * 2]);
#pragma unroll
        for (int nt = 0; nt < 8; nt++) {
            uint32_t b0 = *reinterpret_cast<const uint32_t*>(&sWt[(nt * 8 + g) * LDA + kk + tg * 2]);
            uint32_t b1 = *reinterpret_cast<const uint32_t*>(&sWt[(nt * 8 + g) * LDA + kk + 8 + tg * 2]);
            asm volatile(
                "mma.sync.aligned.m16n8k16.row.col.f32.f16.f16.f32 "
                "{%0,%1,%2,%3}, {%4,%5,%6,%7}, {%8,%9}, {%0,%1,%2,%3};"
                : "+f"(acc[nt][0]), "+f"(acc[nt][1]), "+f"(acc[nt][2]), "+f"(acc[nt][3])
                : "r"(a0), "r"(a1), "r"(a2), "r"(a3), "r"(b0), "r"(b1));
        }
    }
    __syncthreads();

    int grow0 = rowBase + r0, grow1 = grow0 + 8;
    float ds0 = (grow0 < n) ? rowscale[grow0] : 0.f;
    float ds1 = (grow1 < n) ? rowscale[grow1] : 0.f;
#pragma unroll
    for (int nt = 0; nt < 8; nt++) {
        int col = nt * 8 + tg * 2;
        float bx = sBias[col], by = sBias[col + 1];
        *reinterpret_cast<__half2*>(&sC[(r0)     * LDC + col]) =
            __floats2half2_rn((acc[nt][0] + bx) * ds0, (acc[nt][1] + by) * ds0);
        *reinterpret_cast<__half2*>(&sC[(r0 + 8) * LDC + col]) =
            __floats2half2_rn((acc[nt][2] + bx) * ds1, (acc[nt][3] + by) * ds1);
    }
    __syncthreads();

    for (int i = tid; i < 64 * 8; i += 128) {
        int r = i >> 3, q = i & 7;
        int gr = rowBase + r;
        if (gr < n) {
            uint4 v = *reinterpret_cast<const uint4*>(&sC[r * LDC + q * 8]);
            *reinterpret_cast<uint4*>(&C[(size_t)gr * 64 + q * 8]) = v;
        }
    }
}

// ---------------- fused GCN layer (fp16 messages + fp16 in-loop accumulation) --------------
// 4 nodes per warp. Quad-gather UNROLLED x4: 16 edges/iter = 4 csr int4 loads +
// 4 independent LDG.128 gathers in flight (MLP=4) + 16 HADD2.
// Lane group g=lane>>3 owns edge slot g within each quad; lane&7 selects 8 cols (16B).
#define QUAD_ACC(r_)                                                                  \
    {                                                                                 \
        acc0 = __hadd2(acc0, *reinterpret_cast<__half2*>(&(r_).x));                   \
        acc1 = __hadd2(acc1, *reinterpret_cast<__half2*>(&(r_).y));                   \
        acc2 = __hadd2(acc2, *reinterpret_cast<__half2*>(&(r_).z));                   \
        acc3 = __hadd2(acc3, *reinterpret_cast<__half2*>(&(r_).w));                   \
    }

#define SINGLE_ACC(idx_)                                                              \
    {                                                                                 \
        uint4 _r = *reinterpret_cast<const uint4*>(mh + ((size_t)(idx_) << 6) + coff);\
        acc0 = __hfma2(*reinterpret_cast<__half2*>(&_r.x), mskh, acc0);               \
        acc1 = __hfma2(*reinterpret_cast<__half2*>(&_r.y), mskh, acc1);               \
        acc2 = __hfma2(*reinterpret_cast<__half2*>(&_r.z), mskh, acc2);               \
        acc3 = __hfma2(*reinterpret_cast<__half2*>(&_r.w), mskh, acc3);               \
    }

#define QSEL(q_) ((grp == 0) ? (q_).x : (grp == 1) ? (q_).y : (grp == 2) ? (q_).z : (q_).w)

template <bool OUT_HALF>
__global__ void __launch_bounds__(256) k_layer(
        const __half* __restrict__ mh, void* __restrict__ hout,
        const float* __restrict__ W, const float* __restrict__ bias,
        const float* __restrict__ gamma, const float* __restrict__ beta, int n) {
    __shared__ __align__(16) float sW[64 * 64];      // 16 KB
    __shared__ __align__(16) float st[8][4][64];     // 8 KB
    __shared__ float sb[64], sg[64], sbt[64];
    const int tid = threadIdx.x;
    for (int i = tid; i < 64 * 64; i += 256) sW[i] = W[i];
    if (tid < 64) {
        sb[tid] = bias[tid];
        sg[tid] = gamma[tid] * rsqrtf(1.0f + 1e-5f);
        sbt[tid] = beta[tid];
    }
    __syncthreads();

    const int lane = tid & 31, wib = tid >> 5;
    const int vbase = blockIdx.x * 32 + wib * 4;
    const int grp = lane >> 3;                       // edge slot 0..3
    const size_t coff = (size_t)((lane & 7) << 3);   // half offset: 8 halfs per lane
    const __half2 mskh = (grp == 0) ? __floats2half2_rn(1.f, 1.f)
                                    : __floats2half2_rn(0.f, 0.f);

#pragma unroll
    for (int i = 0; i < 4; i++) {
        int v = vbase + i;
        __half2 acc0 = __floats2half2_rn(0.f, 0.f);
        __half2 acc1 = acc0, acc2 = acc0, acc3 = acc0;
        float dv = 0.f;
        if (v < n) {
            dv = g_dis[v];
            SINGLE_ACC(v);                           // self loop (group 0 only)
            int e = g_off[v];
            int end = e + g_deg_in[v];
            while ((e & 3) && e < end) {             // peel to int4 alignment
                SINGLE_ACC(g_csr[e]);
                e++;
            }
            // 16 edges per iteration: 4 csr int4 + 4 independent quad LDG.128
            for (; e + 16 <= end; e += 16) {
                const int4* c4 = reinterpret_cast<const int4*>(g_csr + e);
                int4 q0 = c4[0], q1 = c4[1], q2 = c4[2], q3 = c4[3];
                int i0 = QSEL(q0), i1 = QSEL(q1), i2 = QSEL(q2), i3 = QSEL(q3);
                uint4 r0 = *reinterpret_cast<const uint4*>(mh + ((size_t)i0 << 6) + coff);
                uint4 r1 = *reinterpret_cast<const uint4*>(mh + ((size_t)i1 << 6) + coff);
                uint4 r2 = *reinterpret_cast<const uint4*>(mh + ((size_t)i2 << 6) + coff);
                uint4 r3 = *reinterpret_cast<const uint4*>(mh + ((size_t)i3 << 6) + coff);
                QUAD_ACC(r0);
                QUAD_ACC(r1);
                QUAD_ACC(r2);
                QUAD_ACC(r3);
            }
            for (; e + 4 <= end; e += 4) {           // 4-edge steps
                int4 q = *reinterpret_cast<const int4*>(g_csr + e);
                int idx = QSEL(q);
                uint4 r = *reinterpret_cast<const uint4*>(mh + ((size_t)idx << 6) + coff);
                QUAD_ACC(r);
            }
            while (e < end) {                        // tail <4
                SINGLE_ACC(g_csr[e]);
                e++;
            }
        }
        // fp32 convert + combine 4 groups
        float2 f0 = __half22float2(acc0), f1 = __half22float2(acc1);
        float2 f2 = __half22float2(acc2), f3 = __half22float2(acc3);
        float a[8] = {f0.x, f0.y, f1.x, f1.y, f2.x, f2.y, f3.x, f3.y};
#pragma unroll
        for (int k = 0; k < 8; k++) {
            a[k] += __shfl_xor_sync(0xffffffffu, a[k], 8);
            a[k] += __shfl_xor_sync(0xffffffffu, a[k], 16);
        }
        if (lane < 8) {
            float4* row4 = reinterpret_cast<float4*>(st[wib][i]);
            row4[lane * 2]     = make_float4(a[0] * dv, a[1] * dv, a[2] * dv, a[3] * dv);
            row4[lane * 2 + 1] = make_float4(a[4] * dv, a[5] * dv, a[6] * dv, a[7] * dv);
        }
    }
    __syncwarp();

    float o00 = sb[2 * lane], o01 = sb[2 * lane + 1];
    float o10 = o00, o11 = o01, o20 = o00, o21 = o01, o30 = o00, o31 = o01;
    const float2* sW2 = reinterpret_cast<const float2*>(sW);
#pragma unroll 8
    for (int k = 0; k < 64; k++) {
        float2 w = sW2[k * 32 + lane];
        float t0 = st[wib][0][k], t1 = st[wib][1][k], t2 = st[wib][2][k], t3 = st[wib][3][k];
        o00 = fmaf(t0, w.x, o00); o01 = fmaf(t0, w.y, o01);
        o10 = fmaf(t1, w.x, o10); o11 = fmaf(t1, w.y, o11);
        o20 = fmaf(t2, w.x, o20); o21 = fmaf(t2, w.y, o21);
        o30 = fmaf(t3, w.x, o30); o31 = fmaf(t3, w.y, o31);
    }

    float gx = sg[2 * lane], gy = sg[2 * lane + 1];
    float bx = sbt[2 * lane], by = sbt[2 * lane + 1];
    float ox[4] = {o00, o10, o20, o30};
    float oy[4] = {o01, o11, o21, o31};
#pragma unroll
    for (int i = 0; i < 4; i++) {
        int v = vbase + i;
        if (v < n) {
            float y0 = fmaxf(fmaf(ox[i], gx, bx), 0.f);
            float y1 = fmaxf(fmaf(oy[i], gy, by), 0.f);
            if (OUT_HALF) {
                float dv = g_dis[v];
                reinterpret_cast<__half2*>(hout)[(size_t)v * 32 + lane] =
                    __floats2half2_rn(y0 * dv, y1 * dv);
            } else {
                reinterpret_cast<float2*>(hout)[(size_t)v * 32 + lane] = make_float2(y0, y1);
            }
        }
    }
}

// ---------------- fused epilogue with tensor-core layer-1 ----------------
__global__ void __launch_bounds__(256) k_final(const float* __restrict__ h,
                        const float* __restrict__ Ws1, const float* __restrict__ bs1,
                        const float* __restrict__ Ws2, const float* __restrict__ bs2,
                        const float* __restrict__ Wo1, const float* __restrict__ bo1,
                        const float* __restrict__ Wo2, const float* __restrict__ bo2,
                        const float* __restrict__ Wo3, const float* __restrict__ bo3,
                        float* __restrict__ out, int n) {
    constexpr int LDZ = 136;   // halfs
    constexpr int LDY = 68;    // floats
    __shared__ __align__(16) __half sWt[64 * LDZ];
    __shared__ __align__(16) char  sZY[64 * LDZ * 2];
    __shared__ float sWo2[64 * 32];
    __shared__ float sbo1[64];
    __half* sZ = reinterpret_cast<__half*>(sZY);
    float*  sY1 = reinterpret_cast<float*>(sZY);

    const int tid = threadIdx.x;
    const int lane = tid & 31, wib = tid >> 5;
    const int vBase = blockIdx.x * 64;

    for (int i = tid; i < 128 * 64; i += 256) {
        int k = i >> 6, nn = i & 63;
        sWt[nn * LDZ + k] = __float2half_rn(Wo1[i]);
    }
    for (int i = tid; i < 64 * 32; i += 256) sWo2[i] = Wo2[i];
    if (tid < 64) sbo1[tid] = bo1[tid];

    float dmax = __uint_as_float(g_maxima[0]);
    float imax = __uint_as_float(g_maxima[1]);

#pragma unroll
    for (int i = 0; i < 8; i++) {
        int lr = wib * 8 + i;
        int v = vBase + lr;
        __half2* zrow = reinterpret_cast<__half2*>(&sZ[lr * LDZ]);
        if (v < n) {
            float degf = (float)g_deg_out[v];
            float inflv = g_infl[v];
            float sf0 = (dmax > 0.f) ? (degf / dmax) : degf;
            float sf2 = (imax > 0.f) ? (inflv / imax) : inflv;

            float hid = __ldg(&bs1[lane]) + sf0 * __ldg(&Ws1[lane]) + sf2 * __ldg(&Ws1[64 + lane]);
            hid = fmaxf(hid, 0.f);

            float se0 = __ldg(&bs2[2 * lane]);
            float se1 = __ldg(&bs2[2 * lane + 1]);
#pragma unroll
            for (int k = 0; k < 32; k++) {
                float hk = __shfl_sync(0xffffffffu, hid, k);
                float2 w = __ldg(reinterpret_cast<const float2*>(Ws2) + k * 32 + lane);
                se0 = fmaf(hk, w.x, se0);
                se1 = fmaf(hk, w.y, se1);
            }
            float2 hv = reinterpret_cast<const float2*>(h)[(size_t)v * 32 + lane];
            zrow[lane] = __floats2half2_rn(hv.x, hv.y);
            zrow[32 + lane] = __floats2half2_rn(se0, se1);
        } else {
            zrow[lane] = __floats2half2_rn(0.f, 0.f);
            zrow[32 + lane] = __floats2half2_rn(0.f, 0.f);
        }
    }
    __syncthreads();

    const int tileM = wib >> 1;
    const int nHalf = wib & 1;
    const int g = lane >> 2, tg = lane & 3;
    const int r0 = tileM * 16 + g;

    float acc[4][4];
#pragma unroll
    for (int nt = 0; nt < 4; nt++)
#pragma unroll
        for (int j = 0; j < 4; j++) acc[nt][j] = 0.f;

#pragma unroll
    for (int ks = 0; ks < 8; ks++) {
        const int kk = ks * 16;
        uint32_t a0 = *reinterpret_cast<const uint32_t*>(&sZ[(r0)     * LDZ + kk + tg * 2]);
        uint32_t a1 = *reinterpret_cast<const uint32_t*>(&sZ[(r0 + 8) * LDZ + kk + tg * 2]);
        uint32_t a2 = *reinterpret_cast<const uint32_t*>(&sZ[(r0)     * LDZ + kk + 8 + tg * 2]);
        uint32_t a3 = *reinterpret_cast<const uint32_t*>(&sZ[(r0 + 8) * LDZ + kk + 8 + tg * 2]);
#pragma unroll
        for (int nt = 0; nt < 4; nt++) {
            int brow = nHalf * 32 + nt * 8 + g;
            uint32_t b0 = *reinterpret_cast<const uint32_t*>(&sWt[brow * LDZ + kk + tg * 2]);
            uint32_t b1 = *reinterpret_cast<const uint32_t*>(&sWt[brow * LDZ + kk + 8 + tg * 2]);
            asm volatile(
                "mma.sync.aligned.m16n8k16.row.col.f32.f16.f16.f32 "
                "{%0,%1,%2,%3}, {%4,%5,%6,%7}, {%8,%9}, {%0,%1,%2,%3};"
                : "+f"(acc[nt][0]), "+f"(acc[nt][1]), "+f"(acc[nt][2]), "+f"(acc[nt][3])
                : "r"(a0), "r"(a1), "r"(a2), "r"(a3), "r"(b0), "r"(b1));
        }
    }
    __syncthreads();

#pragma unroll
    for (int nt = 0; nt < 4; nt++) {
        int col = nHalf * 32 + nt * 8 + tg * 2;
        float b0 = sbo1[col], b1 = sbo1[col + 1];
        sY1[(r0)     * LDY + col]     = fmaxf(acc[nt][0] + b0, 0.f);
        sY1[(r0)     * LDY + col + 1] = fmaxf(acc[nt][1] + b1, 0.f);
        sY1[(r0 + 8) * LDY + col]     = fmaxf(acc[nt][2] + b0, 0.f);
        sY1[(r0 + 8) * LDY + col + 1] = fmaxf(acc[nt][3] + b1, 0.f);
    }
    __syncthreads();

    float w3 = __ldg(&Wo3[lane]);
    float b2v = __ldg(&bo2[lane]);
    float b3 = __ldg(bo3);
#pragma unroll
    for (int j = 0; j < 4; j++) {
        int lr0 = wib * 8 + j * 2;
        int lr1 = lr0 + 1;
        float y20 = b2v, y21 = b2v;
        const float* y1a = &sY1[lr0 * LDY];
        const float* y1b = &sY1[lr1 * LDY];
#pragma unroll 16
        for (int k = 0; k < 64; k++) {
            float w2 = sWo2[k * 32 + lane];
            y20 = fmaf(y1a[k], w2, y20);
            y21 = fmaf(y1b[k], w2, y21);
        }
        y20 = fmaxf(y20, 0.f);
        y21 = fmaxf(y21, 0.f);
        float p0 = y20 * w3, p1 = y21 * w3;
#pragma unroll
        for (int off = 16; off; off >>= 1) {
            p0 += __shfl_down_sync(0xffffffffu, p0, off);
            p1 += __shfl_down_sync(0xffffffffu, p1, off);
        }
        if (lane == 0) {
            int v0 = vBase + lr0, v1 = vBase + lr1;
            if (v0 < n) out[v0] = 1.f / (1.f + expf(-(p0 + b3)));
            if (v1 < n) out[v1] = 1.f / (1.f + expf(-(p1 + b3)));
        }
    }
}

// ---------------- launch ----------------
extern "C" void kernel_launch(void* const* d_in, const int* in_sizes, int n_in,
                              void* d_out, int out_size) {
    const float* x     = (const float*)d_in[0];
    const int*   ei    = (const int*)  d_in[1];
    const float* W_in  = (const float*)d_in[2];
    const float* b_in  = (const float*)d_in[3];
    const float* W_gcn = (const float*)d_in[4];
    const float* b_gcn = (const float*)d_in[5];
    const float* gamma = (const float*)d_in[6];
    const float* beta  = (const float*)d_in[7];
    const float* Ws1   = (const float*)d_in[8];
    const float* bs1   = (const float*)d_in[9];
    const float* Ws2   = (const float*)d_in[10];
    const float* bs2   = (const float*)d_in[11];
    const float* Wo1   = (const float*)d_in[12];
    const float* bo1   = (const float*)d_in[13];
    const float* Wo2   = (const float*)d_in[14];
    const float* bo2   = (const float*)d_in[15];
    const float* Wo3   = (const float*)d_in[16];
    const float* bo3   = (const float*)d_in[17];
    float* out = (float*)d_out;

    int n = in_sizes[0] / 128;
    int e = in_sizes[1] / 2;
    if (n > NN) n = NN;
    if (e > EE) e = EE;

    void *pA_, *pB_, *pF_, *pDis_;
    cudaGetSymbolAddress(&pA_, g_mA);
    cudaGetSymbolAddress(&pB_, g_mB);
    cudaGetSymbolAddress(&pF_, g_hF);
    cudaGetSymbolAddress(&pDis_, g_dis);
    __half* pA = (__half*)pA_;
    __half* pB = (__half*)pB_;
    float*  pF = (float*)pF_;
    float*  pDis = (float*)pDis_;

    int nb_n = (n + 255) / 256;
    int nb_e2 = (e / 2 + 255) / 256 + 1;   // 2 edges/thread kernels
    int nb_s = (n + 1023) / 1024;
    int nb_f = (n + 63) / 64;      // k_final: 64 nodes/block
    int nb_l = (n + 31) / 32;      // k_layer: 32 nodes/block
    int nb_m = (n + 63) / 64;      // mma GEMM: 64 rows/block

    k_init<<<nb_n, 256>>>(W_in, n);        // 0
    k_hist<<<nb_e2, 256>>>(ei, e);         // 1 (also captures edge ranks)
    k_scan<<<nb_s, 1024>>>(n);             // 2 (single-wave lookback scan)
    k_scatter<<<nb_e2, 256>>>(ei, e);      // 3 <- ncu-sampled slot (atomic-free)
    k_struct<<<nb_n, 256>>>(n);            // 4

    // input projection (tensor cores): m0 = fp16(dis * (x @ W_in + b_in))
    k_gemm_mma<<<nb_m, 128>>>(x, b_in, pDis, pA, n);

    // 3 fused GCN layers (agg + GEMM + BN + relu); last layer writes fp32 h
    k_layer<true ><<<nb_l, 256>>>(pA, pB, W_gcn + 0 * 4096, b_gcn + 0 * 64, gamma + 0 * 64, beta + 0 * 64, n);
    k_layer<true ><<<nb_l, 256>>>(pB, pA, W_gcn + 1 * 4096, b_gcn + 1 * 64, gamma + 1 * 64, beta + 1 * 64, n);
    k_layer<false><<<nb_l, 256>>>(pA, pF, W_gcn + 2 * 4096, b_gcn + 2 * 64, gamma + 2 * 64, beta + 2 * 64, n);

    // structural MLP + concat + output MLP (tensor-core layer1) + sigmoid
    k_final<<<nb_f, 256>>>(pF, Ws1, bs1, Ws2, bs2, Wo1, bo1, Wo2, bo2, Wo3, bo3, out, n);
}

// round 16
// speedup vs baseline: 1.1146x; 1.0141x over previous
#include <cuda_runtime.h>
#include <cuda_fp16.h>
#include <stdint.h>
#include <math.h>

#define NN 100000
#define EE 3200000
#define HIDN 64

// ---------------- scratch (device globals; no allocation allowed) ----------------
__device__ __align__(128) __half g_mA[NN * HIDN];  // fp16 message ping (128B rows)
__device__ __align__(128) __half g_mB[NN * HIDN];  // fp16 message pong
__device__ __align__(16) float  g_hF[NN * HIDN];   // fp32 final-layer output
__device__ __align__(16) __half g_Wh[64 * 136];    // W_in transposed [n][k], fp16, LDA=136
__device__ __align__(16) int g_csr[EE];  // edge sources sorted by destination
__device__ __align__(16) int g_rank[EE]; // per-edge rank among same-destination edges
__device__ int   g_deg_in[NN];           // in-degree (no self loop)
__device__ int   g_off[NN];              // CSR offsets (exclusive scan of deg_in)
__device__ __align__(16) int2 g_offdeg[NN]; // packed {off, deg_out} for scatter
__device__ int   g_deg_out[NN];          // out-degree (structural)
__device__ float g_dis[NN];              // rsqrt(deg_in + 1)
__device__ float g_infl_sum[NN];
__device__ float g_infl[NN];
__device__ unsigned g_maxima[2];         // [0]=max out-degree bits, [1]=max infl bits
__device__ volatile int g_bsumv[128];    // scan block sums (published)
__device__ volatile int g_sflag[128];    // scan publish flags

// ---------------- init (+ W_in transpose/convert to fp16) ----------------
__global__ void k_init(const float* __restrict__ W, int n) {
    int i = blockIdx.x * blockDim.x + threadIdx.x;
    if (i < n) {
        g_deg_in[i] = 0;
        g_deg_out[i] = 0;
        g_infl_sum[i] = 0.f;
    }
    if (i < 2) g_maxima[i] = 0u;
    if (i < 128) { g_sflag[i] = 0; g_bsumv[i] = 0; }
    if (i < 128 * 64) {                      // coalesced read of W [k][n]
        int k = i >> 6, nn = i & 63;
        g_Wh[nn * 136 + k] = __float2half_rn(W[i]);
    }
}

// ---------------- degree histograms (+ edge rank capture), 2 edges/thread ----------------
__global__ void k_hist(const int* __restrict__ ei, int e) {
    int idx = (blockIdx.x * blockDim.x + threadIdx.x) * 2;
    if (idx >= e) return;
    if (idx + 1 < e) {
        int2 r2 = *reinterpret_cast<const int2*>(ei + idx);
        int2 c2 = *reinterpret_cast<const int2*>(ei + e + idx);
        g_rank[idx]     = atomicAdd(&g_deg_in[c2.x], 1);
        g_rank[idx + 1] = atomicAdd(&g_deg_in[c2.y], 1);
        atomicAdd(&g_deg_out[r2.x], 1);
        atomicAdd(&g_deg_out[r2.y], 1);
    } else {
        int r = ei[idx];
        int c = ei[e + idx];
        g_rank[idx] = atomicAdd(&g_deg_in[c], 1);
        atomicAdd(&g_deg_out[r], 1);
    }
}

// ---------------- single-kernel exclusive scan (shuffle-based) + dis + offdeg pack ----------
// <= 98 blocks of 1024: guaranteed single wave on 148+ SMs -> spin-wait is safe.
__global__ void k_scan(int n) {
    __shared__ int sw[32];       // per-warp totals
    __shared__ int sPre;
    int tid = threadIdx.x;
    int lane = tid & 31, wib = tid >> 5;
    int b = blockIdx.x;
    int i = b * 1024 + tid;
    int val = (i < n) ? g_deg_in[i] : 0;
    if (i < n) g_dis[i] = rsqrtf((float)(val + 1));   // +1 for self loop

    // warp inclusive scan
    int x = val;
#pragma unroll
    for (int o = 1; o < 32; o <<= 1) {
        int t = __shfl_up_sync(0xffffffffu, x, o);
        if (lane >= o) x += t;
    }
    if (lane == 31) sw[wib] = x;
    __syncthreads();
    // warp 0 scans the 32 warp totals (exclusive)
    if (wib == 0) {
        int wv = sw[lane];
        int y = wv;
#pragma unroll
        for (int o = 1; o < 32; o <<= 1) {
            int t = __shfl_up_sync(0xffffffffu, y, o);
            if (lane >= o) y += t;
        }
        sw[lane] = y - wv;   // exclusive warp prefix
        if (lane == 31) {
            g_bsumv[b] = y;  // block total
            __threadfence();
            g_sflag[b] = 1;
        }
    }
    // warp 1: sum predecessors' block totals
    if (wib == 1) {
        bool n0 = (lane      < b), n1 = (lane + 32 < b);
        bool n2 = (lane + 64 < b), n3 = (lane + 96 < b);
        while (true) {
            bool ok = (!n0 || g_sflag[lane]) && (!n1 || g_sflag[lane + 32]) &&
                      (!n2 || g_sflag[lane + 64]) && (!n3 || g_sflag[lane + 96]);
            if (__all_sync(0xffffffffu, ok)) break;
        }
        __threadfence();
        int pre = 0;
        if (n0) pre += g_bsumv[lane];
        if (n1) pre += g_bsumv[lane + 32];
        if (n2) pre += g_bsumv[lane + 64];
        if (n3) pre += g_bsumv[lane + 96];
#pragma unroll
        for (int o = 16; o; o >>= 1) pre += __shfl_down_sync(0xffffffffu, pre, o);
        if (lane == 0) sPre = pre;
    }
    __syncthreads();
    if (i < n) {
        int off = (x - val) + sw[wib] + sPre;   // global exclusive prefix
        g_off[i] = off;
        g_offdeg[i] = make_int2(off, g_deg_out[i]);
    }
}

// ---------------- CSR scatter (atomic-free) + influence sums, 2 edges/thread ----------------
__global__ void k_scatter(const int* __restrict__ ei, int e) {
    int idx = (blockIdx.x * blockDim.x + threadIdx.x) * 2;
    if (idx >= e) return;
    if (idx + 1 < e) {
        int2 r2 = *reinterpret_cast<const int2*>(ei + idx);
        int2 c2 = *reinterpret_cast<const int2*>(ei + e + idx);
        int2 k2 = *reinterpret_cast<const int2*>(g_rank + idx);
        int2 od0 = g_offdeg[c2.x];
        int2 od1 = g_offdeg[c2.y];
        g_csr[od0.x + k2.x] = r2.x;
        g_csr[od1.x + k2.y] = r2.y;
        atomicAdd(&g_infl_sum[r2.x], (float)od0.y);
        atomicAdd(&g_infl_sum[r2.y], (float)od1.y);
    } else {
        int r = ei[idx];
        int c = ei[e + idx];
        int2 od = g_offdeg[c];
        g_csr[od.x + g_rank[idx]] = r;
        atomicAdd(&g_infl_sum[r], (float)od.y);
    }
}

// ---------------- structural finalize (block-reduced maxima) ----------------
__global__ void k_struct(int n) {
    int v = blockIdx.x * blockDim.x + threadIdx.x;
    float degf = 0.f, infl = 0.f;
    if (v < n) {
        degf = (float)g_deg_out[v];
        infl = (degf > 0.f) ? (g_infl_sum[v] / degf) : 0.f;
        g_infl[v] = infl;
    }
#pragma unroll
    for (int off = 16; off; off >>= 1) {
        degf = fmaxf(degf, __shfl_down_sync(0xffffffffu, degf, off));
        infl = fmaxf(infl, __shfl_down_sync(0xffffffffu, infl, off));
    }
    __shared__ float sd[8], si[8];
    int lane = threadIdx.x & 31, wib = threadIdx.x >> 5;
    if (lane == 0) { sd[wib] = degf; si[wib] = infl; }
    __syncthreads();
    if (threadIdx.x == 0) {
        float md = sd[0], mi = si[0];
#pragma unroll
        for (int i = 1; i < 8; i++) { md = fmaxf(md, sd[i]); mi = fmaxf(mi, si[i]); }
        atomicMax(&g_maxima[0], __float_as_uint(md));
        atomicMax(&g_maxima[1], __float_as_uint(mi));
    }
}

// ---------------- tensor-core input GEMM ----------------
__global__ void __launch_bounds__(128) k_gemm_mma(
        const float* __restrict__ A, const float* __restrict__ bias,
        const float* __restrict__ rowscale, __half* __restrict__ C, int n) {
    constexpr int LDA = 136;   // halfs
    constexpr int LDC = 72;    // halfs
    __shared__ __align__(16) __half sA[64 * LDA];
    __shared__ __align__(16) __half sWt[64 * LDA];
    __shared__ float sBias[64];
    __half* sC = sA;

    const int tid = threadIdx.x;
    const int rowBase = blockIdx.x * 64;

    {
        const uint4* src = reinterpret_cast<const uint4*>(g_Wh);
        uint4* dst = reinterpret_cast<uint4*>(sWt);
        for (int i = tid; i < 64 * LDA / 8; i += 128) dst[i] = src[i];
    }
    if (tid < 64) sBias[tid] = bias[tid];

    for (int i = tid; i < 64 * 32; i += 128) {
        int r = i >> 5, c4 = i & 31;
        int gr = rowBase + r;
        float4 v = (gr < n) ? reinterpret_cast<const float4*>(A)[(size_t)gr * 32 + c4]
                            : make_float4(0.f, 0.f, 0.f, 0.f);
        __half2* d2 = reinterpret_cast<__half2*>(&sA[r * LDA + c4 * 4]);
        d2[0] = __floats2half2_rn(v.x, v.y);
        d2[1] = __floats2half2_rn(v.z, v.w);
    }
    __syncthreads();

    const int lane = tid & 31;
    const int warpM = tid >> 5;
    const int g = lane >> 2;
    const int tg = lane & 3;
    const int r0 = warpM * 16 + g;

    float acc[8][4];
#pragma unroll
    for (int nt = 0; nt < 8; nt++)
#pragma unroll
        for (int j = 0; j < 4; j++) acc[nt][j] = 0.f;

#pragma unroll
    for (int ks = 0; ks < 8; ks++) {
        const int kk = ks * 16;
        uint32_t a0 = *reinterpret_cast<const uint32_t*>(&sA[(r0)     * LDA + kk + tg * 2]);
        uint32_t a1 = *reinterpret_cast<const uint32_t*>(&sA[(r0 + 8) * LDA + kk + tg * 2]);
        uint32_t a2 = *reinterpret_cast<const uint32_t*>(&sA[(r0)     * LDA + kk + 8 + tg * 2]);
        uint32_t a3 = *reinterpret_cast<const uint32_t*>(&sA[(r0 + 8) * LDA + kk + 8 + tg * 2]);
#pragma unroll
        for (int nt = 0; nt < 8; nt++) {
            uint32_t b0 = *reinterpret_cast<const uint32_t*>(&sWt[(nt * 8 + g) * LDA + kk + tg * 2]);
            uint32_t b1 = *reinterpret_cast<const uint32_t*>(&sWt[(nt * 8 + g) * LDA + kk + 8 + tg * 2]);
            asm volatile(
                "mma.sync.aligned.m16n8k16.row.col.f32.f16.f16.f32 "
                "{%0,%1,%2,%3}, {%4,%5,%6,%7}, {%8,%9}, {%0,%1,%2,%3};"
                : "+f"(acc[nt][0]), "+f"(acc[nt][1]), "+f"(acc[nt][2]), "+f"(acc[nt][3])
                : "r"(a0), "r"(a1), "r"(a2), "r"(a3), "r"(b0), "r"(b1));
        }
    }
    __syncthreads();

    int grow0 = rowBase + r0, grow1 = grow0 + 8;
    float ds0 = (grow0 < n) ? rowscale[grow0] : 0.f;
    float ds1 = (grow1 < n) ? rowscale[grow1] : 0.f;
#pragma unroll
    for (int nt = 0; nt < 8; nt++) {
        int col = nt * 8 + tg * 2;
        float bx = sBias[col], by = sBias[col + 1];
        *reinterpret_cast<__half2*>(&sC[(r0)     * LDC + col]) =
            __floats2half2_rn((acc[nt][0] + bx) * ds0, (acc[nt][1] + by) * ds0);
        *reinterpret_cast<__half2*>(&sC[(r0 + 8) * LDC + col]) =
            __floats2half2_rn((acc[nt][2] + bx) * ds1, (acc[nt][3] + by) * ds1);
    }
    __syncthreads();

    for (int i = tid; i < 64 * 8; i += 128) {
        int r = i >> 3, q = i & 7;
        int gr = rowBase + r;
        if (gr < n) {
            uint4 v = *reinterpret_cast<const uint4*>(&sC[r * LDC + q * 8]);
            *reinterpret_cast<uint4*>(&C[(size_t)gr * 64 + q * 8]) = v;
        }
    }
}

// ---------------- fused GCN layer (R13 pair-gather, measured-best) ----------------
// 4 nodes per warp. Pair-gather: one LDG.64 covers 2 edges (lanes 0-15 = even
// edge, lanes 16-31 = odd edge; each lane owns 4 columns). csr indices loaded
// as uniform int2 (1 LDG per 2 edges). Halves combined via shfl at the end.
#define PAIR_GATHER(sA_, sB_)                                                        \
    {                                                                                \
        int _idx = (lane < 16) ? (sA_) : (sB_);                                      \
        uint2 _r = *reinterpret_cast<const uint2*>(mh + ((size_t)_idx << 6) + lsel); \
        float2 _p0 = __half22float2(*reinterpret_cast<__half2*>(&_r.x));             \
        float2 _p1 = __half22float2(*reinterpret_cast<__half2*>(&_r.y));             \
        a0 += _p0.x; a1 += _p0.y; a2 += _p1.x; a3 += _p1.y;                          \
    }

#define SINGLE_GATHER(s_)                                                            \
    {                                                                                \
        int _idx = (s_);                                                             \
        uint2 _r = *reinterpret_cast<const uint2*>(mh + ((size_t)_idx << 6) + lsel); \
        float2 _p0 = __half22float2(*reinterpret_cast<__half2*>(&_r.x));             \
        float2 _p1 = __half22float2(*reinterpret_cast<__half2*>(&_r.y));             \
        a0 += _p0.x * msk; a1 += _p0.y * msk; a2 += _p1.x * msk; a3 += _p1.y * msk;  \
    }

template <bool OUT_HALF>
__global__ void __launch_bounds__(256) k_layer(
        const __half* __restrict__ mh, void* __restrict__ hout,
        const float* __restrict__ W, const float* __restrict__ bias,
        const float* __restrict__ gamma, const float* __restrict__ beta, int n) {
    __shared__ __align__(16) float sW[64 * 64];      // 16 KB
    __shared__ __align__(16) float st[8][4][64];     // 8 KB
    __shared__ float sb[64], sg[64], sbt[64];
    const int tid = threadIdx.x;
    for (int i = tid; i < 64 * 64; i += 256) sW[i] = W[i];
    if (tid < 64) {
        sb[tid] = bias[tid];
        sg[tid] = gamma[tid] * rsqrtf(1.0f + 1e-5f);
        sbt[tid] = beta[tid];
    }
    __syncthreads();

    const int lane = tid & 31, wib = tid >> 5;
    const int vbase = blockIdx.x * 32 + wib * 4;
    const int lsel = (lane & 15) << 2;               // half offset within 64-half row
    const float msk = (lane < 16) ? 1.f : 0.f;

#pragma unroll
    for (int i = 0; i < 4; i++) {
        int v = vbase + i;
        float a0 = 0.f, a1 = 0.f, a2 = 0.f, a3 = 0.f;
        float dv = 0.f;
        if (v < n) {
            dv = g_dis[v];
            SINGLE_GATHER(v);                        // self loop (masked to lo half)
            int e = g_off[v];
            int end = e + g_deg_in[v];
            if ((e & 1) && e < end) {                // parity peel (<=1 edge)
                SINGLE_GATHER(g_csr[e]);
                e++;
            }
            for (; e + 8 <= end; e += 8) {           // 8 edges: 4 csr int2 + 4 pair LDGs
                const int2* c2 = reinterpret_cast<const int2*>(g_csr + e);
                int2 q0 = c2[0], q1 = c2[1], q2 = c2[2], q3 = c2[3];
                PAIR_GATHER(q0.x, q0.y);
                PAIR_GATHER(q1.x, q1.y);
                PAIR_GATHER(q2.x, q2.y);
                PAIR_GATHER(q3.x, q3.y);
            }
            for (; e + 2 <= end; e += 2) {           // 2-edge steps
                int2 q = *reinterpret_cast<const int2*>(g_csr + e);
                PAIR_GATHER(q.x, q.y);
            }
            if (e < end) SINGLE_GATHER(g_csr[e]);    // final odd edge
        }
        // combine hi half into lo half, scale, store t row (lanes 0-15)
        a0 += __shfl_down_sync(0xffffffffu, a0, 16);
        a1 += __shfl_down_sync(0xffffffffu, a1, 16);
        a2 += __shfl_down_sync(0xffffffffu, a2, 16);
        a3 += __shfl_down_sync(0xffffffffu, a3, 16);
        if (lane < 16) {
            reinterpret_cast<float4*>(st[wib][i])[lane] =
                make_float4(a0 * dv, a1 * dv, a2 * dv, a3 * dv);
        }
    }
    __syncwarp();

    float o00 = sb[2 * lane], o01 = sb[2 * lane + 1];
    float o10 = o00, o11 = o01, o20 = o00, o21 = o01, o30 = o00, o31 = o01;
    const float2* sW2 = reinterpret_cast<const float2*>(sW);
#pragma unroll 8
    for (int k = 0; k < 64; k++) {
        float2 w = sW2[k * 32 + lane];
        float t0 = st[wib][0][k], t1 = st[wib][1][k], t2 = st[wib][2][k], t3 = st[wib][3][k];
        o00 = fmaf(t0, w.x, o00); o01 = fmaf(t0, w.y, o01);
        o10 = fmaf(t1, w.x, o10); o11 = fmaf(t1, w.y, o11);
        o20 = fmaf(t2, w.x, o20); o21 = fmaf(t2, w.y, o21);
        o30 = fmaf(t3, w.x, o30); o31 = fmaf(t3, w.y, o31);
    }

    float gx = sg[2 * lane], gy = sg[2 * lane + 1];
    float bx = sbt[2 * lane], by = sbt[2 * lane + 1];
    float ox[4] = {o00, o10, o20, o30};
    float oy[4] = {o01, o11, o21, o31};
#pragma unroll
    for (int i = 0; i < 4; i++) {
        int v = vbase + i;
        if (v < n) {
            float y0 = fmaxf(fmaf(ox[i], gx, bx), 0.f);
            float y1 = fmaxf(fmaf(oy[i], gy, by), 0.f);
            if (OUT_HALF) {
                float dv = g_dis[v];
                reinterpret_cast<__half2*>(hout)[(size_t)v * 32 + lane] =
                    __floats2half2_rn(y0 * dv, y1 * dv);
            } else {
                reinterpret_cast<float2*>(hout)[(size_t)v * 32 + lane] = make_float2(y0, y1);
            }
        }
    }
}

// ---------------- fused epilogue with tensor-core layer-1 ----------------
__global__ void __launch_bounds__(256) k_final(const float* __restrict__ h,
                        const float* __restrict__ Ws1, const float* __restrict__ bs1,
                        const float* __restrict__ Ws2, const float* __restrict__ bs2,
                        const float* __restrict__ Wo1, const float* __restrict__ bo1,
                        const float* __restrict__ Wo2, const float* __restrict__ bo2,
                        const float* __restrict__ Wo3, const float* __restrict__ bo3,
                        float* __restrict__ out, int n) {
    constexpr int LDZ = 136;   // halfs
    constexpr int LDY = 68;    // floats
    __shared__ __align__(16) __half sWt[64 * LDZ];
    __shared__ __align__(16) char  sZY[64 * LDZ * 2];
    __shared__ float sWo2[64 * 32];
    __shared__ float sbo1[64];
    __half* sZ = reinterpret_cast<__half*>(sZY);
    float*  sY1 = reinterpret_cast<float*>(sZY);

    const int tid = threadIdx.x;
    const int lane = tid & 31, wib = tid >> 5;
    const int vBase = blockIdx.x * 64;

    for (int i = tid; i < 128 * 64; i += 256) {
        int k = i >> 6, nn = i & 63;
        sWt[nn * LDZ + k] = __float2half_rn(Wo1[i]);
    }
    for (int i = tid; i < 64 * 32; i += 256) sWo2[i] = Wo2[i];
    if (tid < 64) sbo1[tid] = bo1[tid];

    float dmax = __uint_as_float(g_maxima[0]);
    float imax = __uint_as_float(g_maxima[1]);

#pragma unroll
    for (int i = 0; i < 8; i++) {
        int lr = wib * 8 + i;
        int v = vBase + lr;
        __half2* zrow = reinterpret_cast<__half2*>(&sZ[lr * LDZ]);
        if (v < n) {
            float degf = (float)g_deg_out[v];
            float inflv = g_infl[v];
            float sf0 = (dmax > 0.f) ? (degf / dmax) : degf;
            float sf2 = (imax > 0.f) ? (inflv / imax) : inflv;

            float hid = __ldg(&bs1[lane]) + sf0 * __ldg(&Ws1[lane]) + sf2 * __ldg(&Ws1[64 + lane]);
            hid = fmaxf(hid, 0.f);

            float se0 = __ldg(&bs2[2 * lane]);
            float se1 = __ldg(&bs2[2 * lane + 1]);
#pragma unroll
            for (int k = 0; k < 32; k++) {
                float hk = __shfl_sync(0xffffffffu, hid, k);
                float2 w = __ldg(reinterpret_cast<const float2*>(Ws2) + k * 32 + lane);
                se0 = fmaf(hk, w.x, se0);
                se1 = fmaf(hk, w.y, se1);
            }
            float2 hv = reinterpret_cast<const float2*>(h)[(size_t)v * 32 + lane];
            zrow[lane] = __floats2half2_rn(hv.x, hv.y);
            zrow[32 + lane] = __floats2half2_rn(se0, se1);
        } else {
            zrow[lane] = __floats2half2_rn(0.f, 0.f);
            zrow[32 + lane] = __floats2half2_rn(0.f, 0.f);
        }
    }
    __syncthreads();

    const int tileM = wib >> 1;
    const int nHalf = wib & 1;
    const int g = lane >> 2, tg = lane & 3;
    const int r0 = tileM * 16 + g;

    float acc[4][4];
#pragma unroll
    for (int nt = 0; nt < 4; nt++)
#pragma unroll
        for (int j = 0; j < 4; j++) acc[nt][j] = 0.f;

#pragma unroll
    for (int ks = 0; ks < 8; ks++) {
        const int kk = ks * 16;
        uint32_t a0 = *reinterpret_cast<const uint32_t*>(&sZ[(r0)     * LDZ + kk + tg * 2]);
        uint32_t a1 = *reinterpret_cast<const uint32_t*>(&sZ[(r0 + 8) * LDZ + kk + tg * 2]);
        uint32_t a2 = *reinterpret_cast<const uint32_t*>(&sZ[(r0)     * LDZ + kk + 8 + tg * 2]);
        uint32_t a3 = *reinterpret_cast<const uint32_t*>(&sZ[(r0 + 8) * LDZ + kk + 8 + tg * 2]);
#pragma unroll
        for (int nt = 0; nt < 4; nt++) {
            int brow = nHalf * 32 + nt * 8 + g;
            uint32_t b0 = *reinterpret_cast<const uint32_t*>(&sWt[brow * LDZ + kk + tg * 2]);
            uint32_t b1 = *reinterpret_cast<const uint32_t*>(&sWt[brow * LDZ + kk + 8 + tg * 2]);
            asm volatile(
                "mma.sync.aligned.m16n8k16.row.col.f32.f16.f16.f32 "
                "{%0,%1,%2,%3}, {%4,%5,%6,%7}, {%8,%9}, {%0,%1,%2,%3};"
                : "+f"(acc[nt][0]), "+f"(acc[nt][1]), "+f"(acc[nt][2]), "+f"(acc[nt][3])
                : "r"(a0), "r"(a1), "r"(a2), "r"(a3), "r"(b0), "r"(b1));
        }
    }
    __syncthreads();

#pragma unroll
    for (int nt = 0; nt < 4; nt++) {
        int col = nHalf * 32 + nt * 8 + tg * 2;
        float b0 = sbo1[col], b1 = sbo1[col + 1];
        sY1[(r0)     * LDY + col]     = fmaxf(acc[nt][0] + b0, 0.f);
        sY1[(r0)     * LDY + col + 1] = fmaxf(acc[nt][1] + b1, 0.f);
        sY1[(r0 + 8) * LDY + col]     = fmaxf(acc[nt][2] + b0, 0.f);
        sY1[(r0 + 8) * LDY + col + 1] = fmaxf(acc[nt][3] + b1, 0.f);
    }
    __syncthreads();

    float w3 = __ldg(&Wo3[lane]);
    float b2v = __ldg(&bo2[lane]);
    float b3 = __ldg(bo3);
#pragma unroll
    for (int j = 0; j < 4; j++) {
        int lr0 = wib * 8 + j * 2;
        int lr1 = lr0 + 1;
        float y20 = b2v, y21 = b2v;
        const float* y1a = &sY1[lr0 * LDY];
        const float* y1b = &sY1[lr1 * LDY];
#pragma unroll 16
        for (int k = 0; k < 64; k++) {
            float w2 = sWo2[k * 32 + lane];
            y20 = fmaf(y1a[k], w2, y20);
            y21 = fmaf(y1b[k], w2, y21);
        }
        y20 = fmaxf(y20, 0.f);
        y21 = fmaxf(y21, 0.f);
        float p0 = y20 * w3, p1 = y21 * w3;
#pragma unroll
        for (int off = 16; off; off >>= 1) {
            p0 += __shfl_down_sync(0xffffffffu, p0, off);
            p1 += __shfl_down_sync(0xffffffffu, p1, off);
        }
        if (lane == 0) {
            int v0 = vBase + lr0, v1 = vBase + lr1;
            if (v0 < n) out[v0] = 1.f / (1.f + expf(-(p0 + b3)));
            if (v1 < n) out[v1] = 1.f / (1.f + expf(-(p1 + b3)));
        }
    }
}

// ---------------- launch ----------------
extern "C" void kernel_launch(void* const* d_in, const int* in_sizes, int n_in,
                              void* d_out, int out_size) {
    const float* x     = (const float*)d_in[0];
    const int*   ei    = (const int*)  d_in[1];
    const float* W_in  = (const float*)d_in[2];
    const float* b_in  = (const float*)d_in[3];
    const float* W_gcn = (const float*)d_in[4];
    const float* b_gcn = (const float*)d_in[5];
    const float* gamma = (const float*)d_in[6];
    const float* beta  = (const float*)d_in[7];
    const float* Ws1   = (const float*)d_in[8];
    const float* bs1   = (const float*)d_in[9];
    const float* Ws2   = (const float*)d_in[10];
    const float* bs2   = (const float*)d_in[11];
    const float* Wo1   = (const float*)d_in[12];
    const float* bo1   = (const float*)d_in[13];
    const float* Wo2   = (const float*)d_in[14];
    const float* bo2   = (const float*)d_in[15];
    const float* Wo3   = (const float*)d_in[16];
    const float* bo3   = (const float*)d_in[17];
    float* out = (float*)d_out;

    int n = in_sizes[0] / 128;
    int e = in_sizes[1] / 2;
    if (n > NN) n = NN;
    if (e > EE) e = EE;

    void *pA_, *pB_, *pF_, *pDis_;
    cudaGetSymbolAddress(&pA_, g_mA);
    cudaGetSymbolAddress(&pB_, g_mB);
    cudaGetSymbolAddress(&pF_, g_hF);
    cudaGetSymbolAddress(&pDis_, g_dis);
    __half* pA = (__half*)pA_;
    __half* pB = (__half*)pB_;
    float*  pF = (float*)pF_;
    float*  pDis = (float*)pDis_;

    int nb_n = (n + 255) / 256;
    int nb_e2 = (e / 2 + 255) / 256 + 1;   // 2 edges/thread kernels
    int nb_s = (n + 1023) / 1024;
    int nb_f = (n + 63) / 64;      // k_final: 64 nodes/block
    int nb_l = (n + 31) / 32;      // k_layer: 32 nodes/block
    int nb_m = (n + 63) / 64;      // mma GEMM: 64 rows/block

    k_init<<<nb_n, 256>>>(W_in, n);        // 0
    k_hist<<<nb_e2, 256>>>(ei, e);         // 1 (also captures edge ranks)
    k_scan<<<nb_s, 1024>>>(n);             // 2 (shuffle scan + offdeg pack)
    k_scatter<<<nb_e2, 256>>>(ei, e);      // 3 <- ncu-sampled slot (atomic-free, packed)
    k_struct<<<nb_n, 256>>>(n);            // 4

    // input projection (tensor cores): m0 = fp16(dis * (x @ W_in + b_in))
    k_gemm_mma<<<nb_m, 128>>>(x, b_in, pDis, pA, n);

    // 3 fused GCN layers (agg + GEMM + BN + relu); last layer writes fp32 h
    k_layer<true ><<<nb_l, 256>>>(pA, pB, W_gcn + 0 * 4096, b_gcn + 0 * 64, gamma + 0 * 64, beta + 0 * 64, n);
    k_layer<true ><<<nb_l, 256>>>(pB, pA, W_gcn + 1 * 4096, b_gcn + 1 * 64, gamma + 1 * 64, beta + 1 * 64, n);
    k_layer<false><<<nb_l, 256>>>(pA, pF, W_gcn + 2 * 4096, b_gcn + 2 * 64, gamma + 2 * 64, beta + 2 * 64, n);

    // structural MLP + concat + output MLP (tensor-core layer1) + sigmoid
    k_final<<<nb_f, 256>>>(pF, Ws1, bs1, Ws2, bs2, Wo1, bo1, Wo2, bo2, Wo3, bo3, out, n);
}

// round 17
// speedup vs baseline: 1.1340x; 1.0174x over previous
#include <cuda_runtime.h>
#include <cuda_fp16.h>
#include <stdint.h>
#include <math.h>

#define NN 100000
#define EE 3200000
#define HIDN 64

// ---------------- scratch (device globals; no allocation allowed) ----------------
__device__ __align__(128) __half g_mA[NN * HIDN];  // fp16 message ping (128B rows)
__device__ __align__(128) __half g_mB[NN * HIDN];  // fp16 message pong
__device__ __align__(16) float  g_hF[NN * HIDN];   // fp32 final-layer output
__device__ __align__(16) __half g_Wh[64 * 136];    // W_in transposed [n][k], fp16, LDA=136
__device__ __align__(16) int g_csr[EE];  // edge sources sorted by destination
__device__ __align__(16) int g_rank[EE]; // per-edge rank among same-destination edges
__device__ int   g_deg_in[NN];           // in-degree (no self loop)
__device__ int   g_off[NN];              // CSR offsets (exclusive scan of deg_in)
__device__ __align__(16) int2 g_offdeg[NN]; // packed {off, deg_out} for scatter
__device__ int   g_deg_out[NN];          // out-degree (structural)
__device__ float g_dis[NN];              // rsqrt(deg_in + 1)
__device__ float g_infl_sum[NN];
__device__ float g_infl[NN];
__device__ unsigned g_maxima[2];         // [0]=max out-degree bits, [1]=max infl bits
__device__ volatile int g_bsumv[128];    // scan block sums (published)
__device__ volatile int g_sflag[128];    // scan publish flags

// ---------------- init (+ W_in transpose/convert to fp16) ----------------
__global__ void k_init(const float* __restrict__ W, int n) {
    int i = blockIdx.x * blockDim.x + threadIdx.x;
    if (i < n) {
        g_deg_in[i] = 0;
        g_deg_out[i] = 0;
        g_infl_sum[i] = 0.f;
    }
    if (i < 2) g_maxima[i] = 0u;
    if (i < 128) { g_sflag[i] = 0; g_bsumv[i] = 0; }
    if (i < 128 * 64) {                      // coalesced read of W [k][n]
        int k = i >> 6, nn = i & 63;
        g_Wh[nn * 136 + k] = __float2half_rn(W[i]);
    }
}

// ---------------- degree histograms (+ edge rank capture), 2 edges/thread ----------------
__global__ void k_hist(const int* __restrict__ ei, int e) {
    int idx = (blockIdx.x * blockDim.x + threadIdx.x) * 2;
    if (idx >= e) return;
    if (idx + 1 < e) {
        int2 r2 = *reinterpret_cast<const int2*>(ei + idx);
        int2 c2 = *reinterpret_cast<const int2*>(ei + e + idx);
        g_rank[idx]     = atomicAdd(&g_deg_in[c2.x], 1);
        g_rank[idx + 1] = atomicAdd(&g_deg_in[c2.y], 1);
        atomicAdd(&g_deg_out[r2.x], 1);
        atomicAdd(&g_deg_out[r2.y], 1);
    } else {
        int r = ei[idx];
        int c = ei[e + idx];
        g_rank[idx] = atomicAdd(&g_deg_in[c], 1);
        atomicAdd(&g_deg_out[r], 1);
    }
}

// ---------------- single-kernel exclusive scan (shuffle-based) + dis + offdeg pack ----------
// <= 98 blocks of 1024: guaranteed single wave on 148+ SMs -> spin-wait is safe.
__global__ void k_scan(int n) {
    __shared__ int sw[32];       // per-warp totals
    __shared__ int sPre;
    int tid = threadIdx.x;
    int lane = tid & 31, wib = tid >> 5;
    int b = blockIdx.x;
    int i = b * 1024 + tid;
    int val = (i < n) ? g_deg_in[i] : 0;
    if (i < n) g_dis[i] = rsqrtf((float)(val + 1));   // +1 for self loop

    // warp inclusive scan
    int x = val;
#pragma unroll
    for (int o = 1; o < 32; o <<= 1) {
        int t = __shfl_up_sync(0xffffffffu, x, o);
        if (lane >= o) x += t;
    }
    if (lane == 31) sw[wib] = x;
    __syncthreads();
    // warp 0 scans the 32 warp totals (exclusive)
    if (wib == 0) {
        int wv = sw[lane];
        int y = wv;
#pragma unroll
        for (int o = 1; o < 32; o <<= 1) {
            int t = __shfl_up_sync(0xffffffffu, y, o);
            if (lane >= o) y += t;
        }
        sw[lane] = y - wv;   // exclusive warp prefix
        if (lane == 31) {
            g_bsumv[b] = y;  // block total
            __threadfence();
            g_sflag[b] = 1;
        }
    }
    // warp 1: sum predecessors' block totals
    if (wib == 1) {
        bool n0 = (lane      < b), n1 = (lane + 32 < b);
        bool n2 = (lane + 64 < b), n3 = (lane + 96 < b);
        while (true) {
            bool ok = (!n0 || g_sflag[lane]) && (!n1 || g_sflag[lane + 32]) &&
                      (!n2 || g_sflag[lane + 64]) && (!n3 || g_sflag[lane + 96]);
            if (__all_sync(0xffffffffu, ok)) break;
        }
        __threadfence();
        int pre = 0;
        if (n0) pre += g_bsumv[lane];
        if (n1) pre += g_bsumv[lane + 32];
        if (n2) pre += g_bsumv[lane + 64];
        if (n3) pre += g_bsumv[lane + 96];
#pragma unroll
        for (int o = 16; o; o >>= 1) pre += __shfl_down_sync(0xffffffffu, pre, o);
        if (lane == 0) sPre = pre;
    }
    __syncthreads();
    if (i < n) {
        int off = (x - val) + sw[wib] + sPre;   // global exclusive prefix
        g_off[i] = off;
        g_offdeg[i] = make_int2(off, g_deg_out[i]);
    }
}

// ---------------- CSR scatter (atomic-free) + influence sums, 2 edges/thread ----------------
__global__ void k_scatter(const int* __restrict__ ei, int e) {
    int idx = (blockIdx.x * blockDim.x + threadIdx.x) * 2;
    if (idx >= e) return;
    if (idx + 1 < e) {
        int2 r2 = *reinterpret_cast<const int2*>(ei + idx);
        int2 c2 = *reinterpret_cast<const int2*>(ei + e + idx);
        int2 k2 = *reinterpret_cast<const int2*>(g_rank + idx);
        int2 od0 = g_offdeg[c2.x];
        int2 od1 = g_offdeg[c2.y];
        g_csr[od0.x + k2.x] = r2.x;
        g_csr[od1.x + k2.y] = r2.y;
        atomicAdd(&g_infl_sum[r2.x], (float)od0.y);
        atomicAdd(&g_infl_sum[r2.y], (float)od1.y);
    } else {
        int r = ei[idx];
        int c = ei[e + idx];
        int2 od = g_offdeg[c];
        g_csr[od.x + g_rank[idx]] = r;
        atomicAdd(&g_infl_sum[r], (float)od.y);
    }
}

// ---------------- structural finalize (block-reduced maxima) ----------------
__global__ void k_struct(int n) {
    int v = blockIdx.x * blockDim.x + threadIdx.x;
    float degf = 0.f, infl = 0.f;
    if (v < n) {
        degf = (float)g_deg_out[v];
        infl = (degf > 0.f) ? (g_infl_sum[v] / degf) : 0.f;
        g_infl[v] = infl;
    }
#pragma unroll
    for (int off = 16; off; off >>= 1) {
        degf = fmaxf(degf, __shfl_down_sync(0xffffffffu, degf, off));
        infl = fmaxf(infl, __shfl_down_sync(0xffffffffu, infl, off));
    }
    __shared__ float sd[8], si[8];
    int lane = threadIdx.x & 31, wib = threadIdx.x >> 5;
    if (lane == 0) { sd[wib] = degf; si[wib] = infl; }
    __syncthreads();
    if (threadIdx.x == 0) {
        float md = sd[0], mi = si[0];
#pragma unroll
        for (int i = 1; i < 8; i++) { md = fmaxf(md, sd[i]); mi = fmaxf(mi, si[i]); }
        atomicMax(&g_maxima[0], __float_as_uint(md));
        atomicMax(&g_maxima[1], __float_as_uint(mi));
    }
}

// ---------------- tensor-core input GEMM ----------------
__global__ void __launch_bounds__(128) k_gemm_mma(
        const float* __restrict__ A, const float* __restrict__ bias,
        const float* __restrict__ rowscale, __half* __restrict__ C, int n) {
    constexpr int LDA = 136;   // halfs
    constexpr int LDC = 72;    // halfs
    __shared__ __align__(16) __half sA[64 * LDA];
    __shared__ __align__(16) __half sWt[64 * LDA];
    __shared__ float sBias[64];
    __half* sC = sA;

    const int tid = threadIdx.x;
    const int rowBase = blockIdx.x * 64;

    {
        const uint4* src = reinterpret_cast<const uint4*>(g_Wh);
        uint4* dst = reinterpret_cast<uint4*>(sWt);
        for (int i = tid; i < 64 * LDA / 8; i += 128) dst[i] = src[i];
    }
    if (tid < 64) sBias[tid] = bias[tid];

    for (int i = tid; i < 64 * 32; i += 128) {
        int r = i >> 5, c4 = i & 31;
        int gr = rowBase + r;
        float4 v = (gr < n) ? reinterpret_cast<const float4*>(A)[(size_t)gr * 32 + c4]
                            : make_float4(0.f, 0.f, 0.f, 0.f);
        __half2* d2 = reinterpret_cast<__half2*>(&sA[r * LDA + c4 * 4]);
        d2[0] = __floats2half2_rn(v.x, v.y);
        d2[1] = __floats2half2_rn(v.z, v.w);
    }
    __syncthreads();

    const int lane = tid & 31;
    const int warpM = tid >> 5;
    const int g = lane >> 2;
    const int tg = lane & 3;
    const int r0 = warpM * 16 + g;

    float acc[8][4];
#pragma unroll
    for (int nt = 0; nt < 8; nt++)
#pragma unroll
        for (int j = 0; j < 4; j++) acc[nt][j] = 0.f;

#pragma unroll
    for (int ks = 0; ks < 8; ks++) {
        const int kk = ks * 16;
        uint32_t a0 = *reinterpret_cast<const uint32_t*>(&sA[(r0)     * LDA + kk + tg * 2]);
        uint32_t a1 = *reinterpret_cast<const uint32_t*>(&sA[(r0 + 8) * LDA + kk + tg * 2]);
        uint32_t a2 = *reinterpret_cast<const uint32_t*>(&sA[(r0)     * LDA + kk + 8 + tg * 2]);
        uint32_t a3 = *reinterpret_cast<const uint32_t*>(&sA[(r0 + 8) * LDA + kk + 8 + tg * 2]);
#pragma unroll
        for (int nt = 0; nt < 8; nt++) {
            uint32_t b0 = *reinterpret_cast<const uint32_t*>(&sWt[(nt * 8 + g) * LDA + kk + tg * 2]);
            uint32_t b1 = *reinterpret_cast<const uint32_t*>(&sWt[(nt * 8 + g) * LDA + kk + 8 + tg * 2]);
            asm volatile(
                "mma.sync.aligned.m16n8k16.row.col.f32.f16.f16.f32 "
                "{%0,%1,%2,%3}, {%4,%5,%6,%7}, {%8,%9}, {%0,%1,%2,%3};"
                : "+f"(acc[nt][0]), "+f"(acc[nt][1]), "+f"(acc[nt][2]), "+f"(acc[nt][3])
                : "r"(a0), "r"(a1), "r"(a2), "r"(a3), "r"(b0), "r"(b1));
        }
    }
    __syncthreads();

    int grow0 = rowBase + r0, grow1 = grow0 + 8;
    float ds0 = (grow0 < n) ? rowscale[grow0] : 0.f;
    float ds1 = (grow1 < n) ? rowscale[grow1] : 0.f;
#pragma unroll
    for (int nt = 0; nt < 8; nt++) {
        int col = nt * 8 + tg * 2;
        float bx = sBias[col], by = sBias[col + 1];
        *reinterpret_cast<__half2*>(&sC[(r0)     * LDC + col]) =
            __floats2half2_rn((acc[nt][0] + bx) * ds0, (acc[nt][1] + by) * ds0);
        *reinterpret_cast<__half2*>(&sC[(r0 + 8) * LDC + col]) =
            __floats2half2_rn((acc[nt][2] + bx) * ds1, (acc[nt][3] + by) * ds1);
    }
    __syncthreads();

    for (int i = tid; i < 64 * 8; i += 128) {
        int r = i >> 3, q = i & 7;
        int gr = rowBase + r;
        if (gr < n) {
            uint4 v = *reinterpret_cast<const uint4*>(&sC[r * LDC + q * 8]);
            *reinterpret_cast<uint4*>(&C[(size_t)gr * 64 + q * 8]) = v;
        }
    }
}

// ---------------- fused GCN layer (R13 pair-gather, measured-best) ----------------
// 4 nodes per warp. Pair-gather: one LDG.64 covers 2 edges (lanes 0-15 = even
// edge, lanes 16-31 = odd edge; each lane owns 4 columns). csr indices loaded
// as uniform int2 (1 LDG per 2 edges). Halves combined via shfl at the end.
#define PAIR_GATHER(sA_, sB_)                                                        \
    {                                                                                \
        int _idx = (lane < 16) ? (sA_) : (sB_);                                      \
        uint2 _r = *reinterpret_cast<const uint2*>(mh + ((size_t)_idx << 6) + lsel); \
        float2 _p0 = __half22float2(*reinterpret_cast<__half2*>(&_r.x));             \
        float2 _p1 = __half22float2(*reinterpret_cast<__half2*>(&_r.y));             \
        a0 += _p0.x; a1 += _p0.y; a2 += _p1.x; a3 += _p1.y;                          \
    }

#define SINGLE_GATHER(s_)                                                            \
    {                                                                                \
        int _idx = (s_);                                                             \
        uint2 _r = *reinterpret_cast<const uint2*>(mh + ((size_t)_idx << 6) + lsel); \
        float2 _p0 = __half22float2(*reinterpret_cast<__half2*>(&_r.x));             \
        float2 _p1 = __half22float2(*reinterpret_cast<__half2*>(&_r.y));             \
        a0 += _p0.x * msk; a1 += _p0.y * msk; a2 += _p1.x * msk; a3 += _p1.y * msk;  \
    }

template <bool OUT_HALF>
__global__ void __launch_bounds__(256) k_layer(
        const __half* __restrict__ mh, void* __restrict__ hout,
        const float* __restrict__ W, const float* __restrict__ bias,
        const float* __restrict__ gamma, const float* __restrict__ beta, int n) {
    __shared__ __align__(16) float sW[64 * 64];      // 16 KB
    __shared__ __align__(16) float st[8][4][64];     // 8 KB
    __shared__ float sb[64], sg[64], sbt[64];
    const int tid = threadIdx.x;
    for (int i = tid; i < 64 * 64; i += 256) sW[i] = W[i];
    if (tid < 64) {
        sb[tid] = bias[tid];
        sg[tid] = gamma[tid] * rsqrtf(1.0f + 1e-5f);
        sbt[tid] = beta[tid];
    }
    __syncthreads();

    const int lane = tid & 31, wib = tid >> 5;
    const int vbase = blockIdx.x * 32 + wib * 4;
    const int lsel = (lane & 15) << 2;               // half offset within 64-half row
    const float msk = (lane < 16) ? 1.f : 0.f;

#pragma unroll
    for (int i = 0; i < 4; i++) {
        int v = vbase + i;
        float a0 = 0.f, a1 = 0.f, a2 = 0.f, a3 = 0.f;
        float dv = 0.f;
        if (v < n) {
            dv = g_dis[v];
            SINGLE_GATHER(v);                        // self loop (masked to lo half)
            int e = g_off[v];
            int end = e + g_deg_in[v];
            if ((e & 1) && e < end) {                // parity peel (<=1 edge)
                SINGLE_GATHER(g_csr[e]);
                e++;
            }
            for (; e + 8 <= end; e += 8) {           // 8 edges: 4 csr int2 + 4 pair LDGs
                const int2* c2 = reinterpret_cast<const int2*>(g_csr + e);
                int2 q0 = c2[0], q1 = c2[1], q2 = c2[2], q3 = c2[3];
                PAIR_GATHER(q0.x, q0.y);
                PAIR_GATHER(q1.x, q1.y);
                PAIR_GATHER(q2.x, q2.y);
                PAIR_GATHER(q3.x, q3.y);
            }
            for (; e + 2 <= end; e += 2) {           // 2-edge steps
                int2 q = *reinterpret_cast<const int2*>(g_csr + e);
                PAIR_GATHER(q.x, q.y);
            }
            if (e < end) SINGLE_GATHER(g_csr[e]);    // final odd edge
        }
        // combine hi half into lo half, scale, store t row (lanes 0-15)
        a0 += __shfl_down_sync(0xffffffffu, a0, 16);
        a1 += __shfl_down_sync(0xffffffffu, a1, 16);
        a2 += __shfl_down_sync(0xffffffffu, a2, 16);
        a3 += __shfl_down_sync(0xffffffffu, a3, 16);
        if (lane < 16) {
            reinterpret_cast<float4*>(st[wib][i])[lane] =
                make_float4(a0 * dv, a1 * dv, a2 * dv, a3 * dv);
        }
    }
    __syncwarp();

    float o00 = sb[2 * lane], o01 = sb[2 * lane + 1];
    float o10 = o00, o11 = o01, o20 = o00, o21 = o01, o30 = o00, o31 = o01;
    const float2* sW2 = reinterpret_cast<const float2*>(sW);
#pragma unroll 8
    for (int k = 0; k < 64; k++) {
        float2 w = sW2[k * 32 + lane];
        float t0 = st[wib][0][k], t1 = st[wib][1][k], t2 = st[wib][2][k], t3 = st[wib][3][k];
        o00 = fmaf(t0, w.x, o00); o01 = fmaf(t0, w.y, o01);
        o10 = fmaf(t1, w.x, o10); o11 = fmaf(t1, w.y, o11);
        o20 = fmaf(t2, w.x, o20); o21 = fmaf(t2, w.y, o21);
        o30 = fmaf(t3, w.x, o30); o31 = fmaf(t3, w.y, o31);
    }

    float gx = sg[2 * lane], gy = sg[2 * lane + 1];
    float bx = sbt[2 * lane], by = sbt[2 * lane + 1];
    float ox[4] = {o00, o10, o20, o30};
    float oy[4] = {o01, o11, o21, o31};
#pragma unroll
    for (int i = 0; i < 4; i++) {
        int v = vbase + i;
        if (v < n) {
            float y0 = fmaxf(fmaf(ox[i], gx, bx), 0.f);
            float y1 = fmaxf(fmaf(oy[i], gy, by), 0.f);
            if (OUT_HALF) {
                float dv = g_dis[v];
                reinterpret_cast<__half2*>(hout)[(size_t)v * 32 + lane] =
                    __floats2half2_rn(y0 * dv, y1 * dv);
            } else {
                reinterpret_cast<float2*>(hout)[(size_t)v * 32 + lane] = make_float2(y0, y1);
            }
        }
    }
}

// ---------------- fused epilogue with tensor-core layer-1 ----------------
__global__ void __launch_bounds__(256) k_final(const float* __restrict__ h,
                        const float* __restrict__ Ws1, const float* __restrict__ bs1,
                        const float* __restrict__ Ws2, const float* __restrict__ bs2,
                        const float* __restrict__ Wo1, const float* __restrict__ bo1,
                        const float* __restrict__ Wo2, const float* __restrict__ bo2,
                        const float* __restrict__ Wo3, const float* __restrict__ bo3,
                        float* __restrict__ out, int n) {
    constexpr int LDZ = 136;   // halfs
    constexpr int LDY = 68;    // floats
    __shared__ __align__(16) __half sWt[64 * LDZ];
    __shared__ __align__(16) char  sZY[64 * LDZ * 2];
    __shared__ float sWo2[64 * 32];
    __shared__ float sbo1[64];
    __half* sZ = reinterpret_cast<__half*>(sZY);
    float*  sY1 = reinterpret_cast<float*>(sZY);

    const int tid = threadIdx.x;
    const int lane = tid & 31, wib = tid >> 5;
    const int vBase = blockIdx.x * 64;

    for (int i = tid; i < 128 * 64; i += 256) {
        int k = i >> 6, nn = i & 63;
        sWt[nn * LDZ + k] = __float2half_rn(Wo1[i]);
    }
    for (int i = tid; i < 64 * 32; i += 256) sWo2[i] = Wo2[i];
    if (tid < 64) sbo1[tid] = bo1[tid];

    float dmax = __uint_as_float(g_maxima[0]);
    float imax = __uint_as_float(g_maxima[1]);

#pragma unroll
    for (int i = 0; i < 8; i++) {
        int lr = wib * 8 + i;
        int v = vBase + lr;
        __half2* zrow = reinterpret_cast<__half2*>(&sZ[lr * LDZ]);
        if (v < n) {
            float degf = (float)g_deg_out[v];
            float inflv = g_infl[v];
            float sf0 = (dmax > 0.f) ? (degf / dmax) : degf;
            float sf2 = (imax > 0.f) ? (inflv / imax) : inflv;

            float hid = __ldg(&bs1[lane]) + sf0 * __ldg(&Ws1[lane]) + sf2 * __ldg(&Ws1[64 + lane]);
            hid = fmaxf(hid, 0.f);

            float se0 = __ldg(&bs2[2 * lane]);
            float se1 = __ldg(&bs2[2 * lane + 1]);
#pragma unroll
            for (int k = 0; k < 32; k++) {
                float hk = __shfl_sync(0xffffffffu, hid, k);
                float2 w = __ldg(reinterpret_cast<const float2*>(Ws2) + k * 32 + lane);
                se0 = fmaf(hk, w.x, se0);
                se1 = fmaf(hk, w.y, se1);
            }
            float2 hv = reinterpret_cast<const float2*>(h)[(size_t)v * 32 + lane];
            zrow[lane] = __floats2half2_rn(hv.x, hv.y);
            zrow[32 + lane] = __floats2half2_rn(se0, se1);
        } else {
            zrow[lane] = __floats2half2_rn(0.f, 0.f);
            zrow[32 + lane] = __floats2half2_rn(0.f, 0.f);
        }
    }
    __syncthreads();

    const int tileM = wib >> 1;
    const int nHalf = wib & 1;
    const int g = lane >> 2, tg = lane & 3;
    const int r0 = tileM * 16 + g;

    float acc[4][4];
#pragma unroll
    for (int nt = 0; nt < 4; nt++)
#pragma unroll
        for (int j = 0; j < 4; j++) acc[nt][j] = 0.f;

#pragma unroll
    for (int ks = 0; ks < 8; ks++) {
        const int kk = ks * 16;
        uint32_t a0 = *reinterpret_cast<const uint32_t*>(&sZ[(r0)     * LDZ + kk + tg * 2]);
        uint32_t a1 = *reinterpret_cast<const uint32_t*>(&sZ[(r0 + 8) * LDZ + kk + tg * 2]);
        uint32_t a2 = *reinterpret_cast<const uint32_t*>(&sZ[(r0)     * LDZ + kk + 8 + tg * 2]);
        uint32_t a3 = *reinterpret_cast<const uint32_t*>(&sZ[(r0 + 8) * LDZ + kk + 8 + tg * 2]);
#pragma unroll
        for (int nt = 0; nt < 4; nt++) {
            int brow = nHalf * 32 + nt * 8 + g;
            uint32_t b0 = *reinterpret_cast<const uint32_t*>(&sWt[brow * LDZ + kk + tg * 2]);
            uint32_t b1 = *reinterpret_cast<const uint32_t*>(&sWt[brow * LDZ + kk + 8 + tg * 2]);
            asm volatile(
                "mma.sync.aligned.m16n8k16.row.col.f32.f16.f16.f32 "
                "{%0,%1,%2,%3}, {%4,%5,%6,%7}, {%8,%9}, {%0,%1,%2,%3};"
                : "+f"(acc[nt][0]), "+f"(acc[nt][1]), "+f"(acc[nt][2]), "+f"(acc[nt][3])
                : "r"(a0), "r"(a1), "r"(a2), "r"(a3), "r"(b0), "r"(b1));
        }
    }
    __syncthreads();

#pragma unroll
    for (int nt = 0; nt < 4; nt++) {
        int col = nHalf * 32 + nt * 8 + tg * 2;
        float b0 = sbo1[col], b1 = sbo1[col + 1];
        sY1[(r0)     * LDY + col]     = fmaxf(acc[nt][0] + b0, 0.f);
        sY1[(r0)     * LDY + col + 1] = fmaxf(acc[nt][1] + b1, 0.f);
        sY1[(r0 + 8) * LDY + col]     = fmaxf(acc[nt][2] + b0, 0.f);
        sY1[(r0 + 8) * LDY + col + 1] = fmaxf(acc[nt][3] + b1, 0.f);
    }
    __syncthreads();

    float w3 = __ldg(&Wo3[lane]);
    float b2v = __ldg(&bo2[lane]);
    float b3 = __ldg(bo3);
#pragma unroll
    for (int j = 0; j < 4; j++) {
        int lr0 = wib * 8 + j * 2;
        int lr1 = lr0 + 1;
        float y20 = b2v, y21 = b2v;
        const float* y1a = &sY1[lr0 * LDY];
        const float* y1b = &sY1[lr1 * LDY];
#pragma unroll 16
        for (int k = 0; k < 64; k++) {
            float w2 = sWo2[k * 32 + lane];
            y20 = fmaf(y1a[k], w2, y20);
            y21 = fmaf(y1b[k], w2, y21);
        }
        y20 = fmaxf(y20, 0.f);
        y21 = fmaxf(y21, 0.f);
        float p0 = y20 * w3, p1 = y21 * w3;
#pragma unroll
        for (int off = 16; off; off >>= 1) {
            p0 += __shfl_down_sync(0xffffffffu, p0, off);
            p1 += __shfl_down_sync(0xffffffffu, p1, off);
        }
        if (lane == 0) {
            int v0 = vBase + lr0, v1 = vBase + lr1;
            if (v0 < n) out[v0] = 1.f / (1.f + expf(-(p0 + b3)));
            if (v1 < n) out[v1] = 1.f / (1.f + expf(-(p1 + b3)));
        }
    }
}

// ---------------- launch ----------------
extern "C" void kernel_launch(void* const* d_in, const int* in_sizes, int n_in,
                              void* d_out, int out_size) {
    const float* x     = (const float*)d_in[0];
    const int*   ei    = (const int*)  d_in[1];
    const float* W_in  = (const float*)d_in[2];
    const float* b_in  = (const float*)d_in[3];
    const float* W_gcn = (const float*)d_in[4];
    const float* b_gcn = (const float*)d_in[5];
    const float* gamma = (const float*)d_in[6];
    const float* beta  = (const float*)d_in[7];
    const float* Ws1   = (const float*)d_in[8];
    const float* bs1   = (const float*)d_in[9];
    const float* Ws2   = (const float*)d_in[10];
    const float* bs2   = (const float*)d_in[11];
    const float* Wo1   = (const float*)d_in[12];
    const float* bo1   = (const float*)d_in[13];
    const float* Wo2   = (const float*)d_in[14];
    const float* bo2   = (const float*)d_in[15];
    const float* Wo3   = (const float*)d_in[16];
    const float* bo3   = (const float*)d_in[17];
    float* out = (float*)d_out;

    int n = in_sizes[0] / 128;
    int e = in_sizes[1] / 2;
    if (n > NN) n = NN;
    if (e > EE) e = EE;

    void *pA_, *pB_, *pF_, *pDis_;
    cudaGetSymbolAddress(&pA_, g_mA);
    cudaGetSymbolAddress(&pB_, g_mB);
    cudaGetSymbolAddress(&pF_, g_hF);
    cudaGetSymbolAddress(&pDis_, g_dis);
    __half* pA = (__half*)pA_;
    __half* pB = (__half*)pB_;
    float*  pF = (float*)pF_;
    float*  pDis = (float*)pDis_;

    // one-time side stream + fork/join events (host objects; created before capture)
    static cudaStream_t s2 = 0;
    static cudaEvent_t evFork = 0, evJoin = 0;
    if (s2 == 0) {
        cudaStreamCreateWithFlags(&s2, cudaStreamNonBlocking);
        cudaEventCreateWithFlags(&evFork, cudaEventDisableTiming);
        cudaEventCreateWithFlags(&evJoin, cudaEventDisableTiming);
    }

    int nb_n = (n + 255) / 256;
    int nb_e2 = (e / 2 + 255) / 256 + 1;   // 2 edges/thread kernels
    int nb_s = (n + 1023) / 1024;
    int nb_f = (n + 63) / 64;      // k_final: 64 nodes/block
    int nb_l = (n + 31) / 32;      // k_layer: 32 nodes/block
    int nb_m = (n + 63) / 64;      // mma GEMM: 64 rows/block

    k_init<<<nb_n, 256>>>(W_in, n);
    k_hist<<<nb_e2, 256>>>(ei, e);
    k_scan<<<nb_s, 1024>>>(n);

    // fork: gemm (needs g_Wh + g_dis only) runs on s2 concurrently with scatter+struct
    cudaEventRecord(evFork, 0);
    cudaStreamWaitEvent(s2, evFork, 0);
    k_gemm_mma<<<nb_m, 128, 0, s2>>>(x, b_in, pDis, pA, n);
    cudaEventRecord(evJoin, s2);

    k_scatter<<<nb_e2, 256>>>(ei, e);      // main stream, overlapped with gemm
    k_struct<<<nb_n, 256>>>(n);

    // join before layers (need csr + messages)
    cudaStreamWaitEvent(0, evJoin, 0);

    // 3 fused GCN layers (agg + GEMM + BN + relu); last layer writes fp32 h
    k_layer<true ><<<nb_l, 256>>>(pA, pB, W_gcn + 0 * 4096, b_gcn + 0 * 64, gamma + 0 * 64, beta + 0 * 64, n);
    k_layer<true ><<<nb_l, 256>>>(pB, pA, W_gcn + 1 * 4096, b_gcn + 1 * 64, gamma + 1 * 64, beta + 1 * 64, n);
    k_layer<false><<<nb_l, 256>>>(pA, pF, W_gcn + 2 * 4096, b_gcn + 2 * 64, gamma + 2 * 64, beta + 2 * 64, n);

    // structural MLP + concat + output MLP (tensor-core layer1) + sigmoid
    k_final<<<nb_f, 256>>>(pF, Ws1, bs1, Ws2, bs2, Wo1, bo1, Wo2, bo2, Wo3, bo3, out, n);
}